// round 8
// baseline (speedup 1.0000x reference)
#include <cuda_runtime.h>
#include <math.h>
#include <stdint.h>

// Problem constants
#define BATCH 8
#define CIN   256
#define NSEQ  4096
#define DKQ   64
#define DOUT  256

// Attention tiling
#define BM 128   // query rows per CTA (8 warps x 16)
#define BK 32    // key rows per pipelined tile
#define NTILES (NSEQ / BK)

// Scratch (device globals)
__device__ float g_q[(size_t)BATCH * NSEQ * DKQ];    // [b][n][64], full fp32, scaled log2e/8
__device__ float g_khi[(size_t)BATCH * NSEQ * DKQ];  // [b][n][64], tf32 hi, COLUMN-INTERLEAVED
__device__ float g_klo[(size_t)BATCH * NSEQ * DKQ];  // [b][n][64], tf32 lo, COLUMN-INTERLEAVED
__device__ float g_v[(size_t)BATCH * NSEQ * DOUT];   // [b][n][256], tf32-truncated

__device__ __forceinline__ float tf32_hi(float x) {
    return __uint_as_float(__float_as_uint(x) & 0xFFFFE000u);
}
__device__ __forceinline__ float fast_exp2(float x) {
    float r;
    asm("ex2.approx.ftz.f32 %0, %1;" : "=f"(r) : "f"(x));
    return r;
}
__device__ __forceinline__ uint32_t smem_u32(const void* p) {
    uint32_t a;
    asm("{ .reg .u64 t; cvta.to.shared.u64 t, %1; cvt.u32.u64 %0, t; }" : "=r"(a) : "l"(p));
    return a;
}
__device__ __forceinline__ void cp_async16(uint32_t dst, const void* src) {
    asm volatile("cp.async.cg.shared.global [%0], [%1], 16;" :: "r"(dst), "l"(src));
}
#define CP_COMMIT() asm volatile("cp.async.commit_group;" ::: "memory")
#define CP_WAIT(N)  asm volatile("cp.async.wait_group %0;" :: "n"(N) : "memory")

// packed f32x2 helpers for projection
__device__ __forceinline__ unsigned long long pack2(float a, float b) {
    unsigned long long r;
    asm("mov.b64 %0, {%1, %2};" : "=l"(r) : "f"(a), "f"(b));
    return r;
}
__device__ __forceinline__ void ffma2(unsigned long long& acc,
                                      unsigned long long a, unsigned long long b) {
    asm("fma.rn.f32x2 %0, %1, %2, %3;" : "=l"(acc) : "l"(a), "l"(b), "l"(acc));
}
__device__ __forceinline__ float2 unpack2(unsigned long long v) {
    float2 r;
    asm("mov.b64 {%0, %1}, %2;" : "=f"(r.x), "=f"(r.y) : "l"(v));
    return r;
}

// m16n8k8 tf32 mma: D += A x B (row.col), accum fp32
__device__ __forceinline__ void mma8(float4& d,
                                     uint32_t a0, uint32_t a1, uint32_t a2, uint32_t a3,
                                     uint32_t b0, uint32_t b1) {
    asm("mma.sync.aligned.m16n8k8.row.col.f32.tf32.tf32.f32 "
        "{%0,%1,%2,%3}, {%4,%5,%6,%7}, {%8,%9}, {%0,%1,%2,%3};"
        : "+f"(d.x), "+f"(d.y), "+f"(d.z), "+f"(d.w)
        : "r"(a0), "r"(a1), "r"(a2), "r"(a3), "r"(b0), "r"(b1));
}

// ==================== projection kernel ====================
__global__ __launch_bounds__(256) void proj_kernel(const float* __restrict__ x,
                                                   const float* __restrict__ Wq,
                                                   const float* __restrict__ Wk,
                                                   const float* __restrict__ Wv) {
    const int n0    = blockIdx.x * 64;
    const int jtile = blockIdx.y;      // 0:q  1:k  2..5:v chunks
    const int b     = blockIdx.z;

    const float* W;
    int j0;
    float scale;
    if (jtile == 0)      { W = Wq; j0 = 0;            scale = 0.125f * 1.4426950408889634f; }
    else if (jtile == 1) { W = Wk; j0 = 0;            scale = 1.0f; }
    else                 { W = Wv; j0 = (jtile-2)*64; scale = 1.0f; }

    __shared__ float xs[16][64];
    __shared__ float wt[16][64];

    const int t  = threadIdx.x;
    const int tn = t >> 4;
    const int tj = t & 15;

    unsigned long long acc2[4][2];
    #pragma unroll
    for (int i = 0; i < 4; i++) { acc2[i][0] = 0ull; acc2[i][1] = 0ull; }

    for (int c0 = 0; c0 < CIN; c0 += 16) {
        {
            int cc = t >> 4;
            int nn = (t & 15) * 4;
            float4 xv = *(const float4*)&x[((size_t)(b * CIN + c0 + cc)) * NSEQ + n0 + nn];
            *(float4*)&xs[cc][nn] = xv;
        }
        {
            int jj = t >> 2;
            int cp = (t & 3) * 4;
            float4 wv = *(const float4*)&W[(size_t)(j0 + jj) * CIN + c0 + cp];
            wt[cp + 0][jj] = wv.x;
            wt[cp + 1][jj] = wv.y;
            wt[cp + 2][jj] = wv.z;
            wt[cp + 3][jj] = wv.w;
        }
        __syncthreads();
        #pragma unroll
        for (int c = 0; c < 16; c++) {
            ulonglong2 b2 = *(const ulonglong2*)&wt[c][4 * tj];
            #pragma unroll
            for (int i = 0; i < 4; i++) {
                float a = xs[c][4 * tn + i];
                unsigned long long aa = pack2(a, a);
                ffma2(acc2[i][0], aa, b2.x);
                ffma2(acc2[i][1], aa, b2.y);
            }
        }
        __syncthreads();
    }

    if (jtile == 1) {
        // K: hi/lo split, column-interleaved: col c -> (c&3)*2 + ((c>>2)&1) + (c>>3)*8
        // This thread's cols are c = 4*tj + i2, i2=0..3  ->  pos = 2*i2 + (tj&1) + 8*(tj>>1)
        const int pbase = (tj & 1) + 8 * (tj >> 1);
        #pragma unroll
        for (int i = 0; i < 4; i++) {
            int n = n0 + 4 * tn + i;
            size_t base = ((size_t)b * NSEQ + n) * DKQ;
            float2 lo2 = unpack2(acc2[i][0]);
            float2 hi2 = unpack2(acc2[i][1]);
            float vv[4] = { lo2.x, lo2.y, hi2.x, hi2.y };
            #pragma unroll
            for (int i2 = 0; i2 < 4; i2++) {
                float h = tf32_hi(vv[i2]);
                float l = tf32_hi(vv[i2] - h);
                g_khi[base + pbase + 2 * i2] = h;
                g_klo[base + pbase + 2 * i2] = l;
            }
        }
    } else {
        float* outp = (jtile == 0) ? g_q : g_v;
        int odim = (jtile >= 2) ? DOUT : DKQ;
        bool trunc = (jtile >= 2);
        #pragma unroll
        for (int i = 0; i < 4; i++) {
            int n = n0 + 4 * tn + i;
            size_t base = ((size_t)b * NSEQ + n) * odim + j0 + 4 * tj;
            float2 lo2 = unpack2(acc2[i][0]);
            float2 hi2 = unpack2(acc2[i][1]);
            float4 v = make_float4(lo2.x * scale, lo2.y * scale, hi2.x * scale, hi2.y * scale);
            if (trunc) v = make_float4(tf32_hi(v.x), tf32_hi(v.y), tf32_hi(v.z), tf32_hi(v.w));
            *(float4*)&outp[base] = v;
        }
    }
}

// ==================== cp.async double-buffered flash attention ====================
// 256 threads = 8 warps x 16 query rows; BK=32, 2-stage pipeline.
// SMEM (floats):
//   KBUF: 2 stages x (KH 32x72 + KL 32x72) = 9216      @ 0
//   VBUF: 2 stages x (32x260)              = 16640     @ 9216
//   P:    128x36                           = 4608      @ 25856
#define KBUF_O 0
#define VBUF_O 9216
#define P_O    25856
#define SMEM_FLOATS 30464   // 121856 bytes
#define KSTG 4608           // floats per K stage (hi+lo)
#define VSTG 8320           // floats per V stage

__global__ __launch_bounds__(256, 1) void attn_mma(float* __restrict__ out) {
    extern __shared__ float sm[];
    float* sP = sm + P_O;
    const uint32_t smb = smem_u32(sm);

    const int tid = threadIdx.x;
    const int w   = tid >> 5;
    const int ln  = tid & 31;
    const int l4  = ln >> 2;   // 0..7
    const int lm4 = ln & 3;    // 0..3
    const int b   = blockIdx.y;
    const int n0  = blockIdx.x * BM;

    // ---- stage Q through KBUF region, build Qh/Ql fragments in registers ----
    uint32_t qh0[8], qh1[8], qh2[8], qh3[8];
    uint32_t ql0[8], ql1[8], ql2[8], ql3[8];
    {
        float* sQ = sm;   // 128 x 68 = 8704 <= 9216 (KBUF region, pre-pipeline)
        const float* qg = g_q + ((size_t)b * NSEQ + n0) * DKQ;
        #pragma unroll
        for (int it = 0; it < 8; it++) {
            int i = tid + it * 256;
            int r = i >> 4, c4 = i & 15;
            *(float4*)&sQ[r * 68 + 4 * c4] = *(const float4*)&qg[(size_t)r * DKQ + 4 * c4];
        }
        __syncthreads();
        const int r0 = (w * 16 + l4) * 68;
        const int r1 = r0 + 8 * 68;
        #pragma unroll
        for (int kt = 0; kt < 8; kt++) {
            int c0 = kt * 8 + lm4;
            float v00 = sQ[r0 + c0],     v10 = sQ[r1 + c0];
            float v01 = sQ[r0 + c0 + 4], v11 = sQ[r1 + c0 + 4];
            float h00 = tf32_hi(v00), h10 = tf32_hi(v10);
            float h01 = tf32_hi(v01), h11 = tf32_hi(v11);
            qh0[kt] = __float_as_uint(h00); qh1[kt] = __float_as_uint(h10);
            qh2[kt] = __float_as_uint(h01); qh3[kt] = __float_as_uint(h11);
            ql0[kt] = __float_as_uint(tf32_hi(v00 - h00));
            ql1[kt] = __float_as_uint(tf32_hi(v10 - h10));
            ql2[kt] = __float_as_uint(tf32_hi(v01 - h01));
            ql3[kt] = __float_as_uint(tf32_hi(v11 - h11));
        }
        __syncthreads();   // done reading sQ before cp.async overwrites KBUF
    }

    // per-thread cp.async task constants
    const int k_arr = tid >> 7;          // with it-loop: i = tid + it*256, arr = i>>9
    (void)k_arr;

    // ---- issue tile 0 ----
    {
        const int k0 = 0;
        #pragma unroll
        for (int it = 0; it < 4; it++) {
            int i = tid + it * 256;
            int arr = i >> 9, r = (i >> 4) & 31, c = i & 15;
            const float* src = (arr ? g_klo : g_khi) +
                               ((size_t)b * NSEQ + k0 + r) * DKQ + c * 4;
            uint32_t dst = smb + (uint32_t)(KBUF_O + arr * 2304) * 4 + r * 288 + c * 16;
            cp_async16(dst, src);
        }
        #pragma unroll
        for (int it = 0; it < 8; it++) {
            int i = tid + it * 256;
            int r = i >> 6, c = i & 63;
            const float* src = g_v + ((size_t)b * NSEQ + k0 + r) * DOUT + c * 4;
            uint32_t dst = smb + (uint32_t)VBUF_O * 4 + r * 1040 + c * 16;
            cp_async16(dst, src);
        }
        CP_COMMIT();
    }

    float4 O[32];
    #pragma unroll
    for (int nt = 0; nt < 32; nt++) O[nt] = make_float4(0.f, 0.f, 0.f, 0.f);
    float lsumA = 0.f, lsumB = 0.f;

    const int prow = (w * 16 + l4) * 36;
    const uint32_t* sPu = (const uint32_t*)sP;

    #pragma unroll 1
    for (int t = 0; t < NTILES; t++) {
        const int stage = t & 1;

        // ---- issue tile t+1 into the other stage ----
        if (t + 1 < NTILES) {
            const int k0n = (t + 1) * BK;
            const int stn = (t + 1) & 1;
            #pragma unroll
            for (int it = 0; it < 4; it++) {
                int i = tid + it * 256;
                int arr = i >> 9, r = (i >> 4) & 31, c = i & 15;
                const float* src = (arr ? g_klo : g_khi) +
                                   ((size_t)b * NSEQ + k0n + r) * DKQ + c * 4;
                uint32_t dst = smb + (uint32_t)(KBUF_O + stn * KSTG + arr * 2304) * 4
                             + r * 288 + c * 16;
                cp_async16(dst, src);
            }
            #pragma unroll
            for (int it = 0; it < 8; it++) {
                int i = tid + it * 256;
                int r = i >> 6, c = i & 63;
                const float* src = g_v + ((size_t)b * NSEQ + k0n + r) * DOUT + c * 4;
                uint32_t dst = smb + (uint32_t)(VBUF_O + stn * VSTG) * 4 + r * 1040 + c * 16;
                cp_async16(dst, src);
            }
            CP_COMMIT();
            CP_WAIT(1);   // tile t complete
        } else {
            CP_WAIT(0);
        }
        __syncthreads();   // tile t visible to all warps

        const float* sKh = sm + KBUF_O + stage * KSTG;
        const float* sKl = sKh + 2304;
        const float* sV  = sm + VBUF_O + stage * VSTG;

        // ---- S = Qhi*(Khi+Klo) + Qlo*Khi  (3-pass tf32), S is 16x32 per warp ----
        float4 S[4];
        #pragma unroll
        for (int nt = 0; nt < 4; nt++) S[nt] = make_float4(0.f, 0.f, 0.f, 0.f);

        #pragma unroll
        for (int kt = 0; kt < 8; kt++) {
            #pragma unroll
            for (int nt = 0; nt < 4; nt++) {
                const int bc = (nt * 8 + l4) * 72 + kt * 8 + lm4 * 2;
                float2 kh = *(const float2*)&sKh[bc];
                float2 kl = *(const float2*)&sKl[bc];
                uint32_t khx = __float_as_uint(kh.x), khy = __float_as_uint(kh.y);
                mma8(S[nt], qh0[kt], qh1[kt], qh2[kt], qh3[kt], khx, khy);
                mma8(S[nt], qh0[kt], qh1[kt], qh2[kt], qh3[kt],
                     __float_as_uint(kl.x), __float_as_uint(kl.y));
                mma8(S[nt], ql0[kt], ql1[kt], ql2[kt], ql3[kt], khx, khy);
            }
        }

        // ---- softmax (log2 domain, no max subtraction); P truncated, lsum from p-hat ----
        #pragma unroll
        for (int nt = 0; nt < 4; nt++) {
            float p0 = tf32_hi(fast_exp2(S[nt].x));
            float p1 = tf32_hi(fast_exp2(S[nt].y));
            float p2 = tf32_hi(fast_exp2(S[nt].z));
            float p3 = tf32_hi(fast_exp2(S[nt].w));
            lsumA += p0 + p1;
            lsumB += p2 + p3;
            const int pc = prow + nt * 8 + 2 * lm4;
            *(float2*)&sP[pc]          = make_float2(p0, p1);
            *(float2*)&sP[pc + 8 * 36] = make_float2(p2, p3);
        }
        __syncwarp();   // P rows are warp-private

        // ---- O += P * V ----
        #pragma unroll
        for (int kt = 0; kt < 4; kt++) {
            const int ac = prow + kt * 8 + lm4;
            uint32_t p0 = sPu[ac],     p1 = sPu[ac + 8 * 36];
            uint32_t p2 = sPu[ac + 4], p3 = sPu[ac + 8 * 36 + 4];
            const int vb0 = (kt * 8 + lm4) * 260 + l4;
            const int vb1 = vb0 + 4 * 260;
            #pragma unroll
            for (int nt = 0; nt < 32; nt++) {
                uint32_t v0 = __float_as_uint(sV[vb0 + nt * 8]);
                uint32_t v1 = __float_as_uint(sV[vb1 + nt * 8]);
                mma8(O[nt], p0, p1, p2, p3, v0, v1);
            }
        }
        __syncthreads();   // all warps done with stage before t+1's cp.async reuses it
    }

    // ---- epilogue ----
    lsumA += __shfl_xor_sync(0xffffffffu, lsumA, 1);
    lsumA += __shfl_xor_sync(0xffffffffu, lsumA, 2);
    lsumB += __shfl_xor_sync(0xffffffffu, lsumB, 1);
    lsumB += __shfl_xor_sync(0xffffffffu, lsumB, 2);
    float invA = 1.0f / lsumA;
    float invB = 1.0f / lsumB;

    const int n = n0 + w * 16 + l4;
    float* ob = out + (size_t)b * DOUT * NSEQ + n;
    #pragma unroll
    for (int nt = 0; nt < 32; nt++) {
        int o = nt * 8 + 2 * lm4;
        ob[(size_t)o * NSEQ]           = O[nt].x * invA;
        ob[(size_t)(o + 1) * NSEQ]     = O[nt].y * invA;
        ob[(size_t)o * NSEQ + 8]       = O[nt].z * invB;
        ob[(size_t)(o + 1) * NSEQ + 8] = O[nt].w * invB;
    }
}

extern "C" void kernel_launch(void* const* d_in, const int* in_sizes, int n_in,
                              void* d_out, int out_size) {
    (void)in_sizes; (void)n_in; (void)out_size;
    const float* x  = (const float*)d_in[0];
    const float* Wq = (const float*)d_in[1];
    const float* Wk = (const float*)d_in[2];
    const float* Wv = (const float*)d_in[3];
    float* out = (float*)d_out;

    cudaFuncSetAttribute(attn_mma, cudaFuncAttributeMaxDynamicSharedMemorySize,
                         SMEM_FLOATS * (int)sizeof(float));

    dim3 gp(NSEQ / 64, 6, BATCH);
    proj_kernel<<<gp, 256>>>(x, Wq, Wk, Wv);

    dim3 ga(NSEQ / BM, BATCH);
    attn_mma<<<ga, 256, SMEM_FLOATS * sizeof(float)>>>(out);
}

// round 9
// speedup vs baseline: 1.2300x; 1.2300x over previous
#include <cuda_runtime.h>
#include <math.h>
#include <stdint.h>

// Problem constants
#define BATCH 8
#define CIN   256
#define NSEQ  4096
#define DKQ   64
#define DOUT  256

// Attention tiling
#define BM 128   // query rows per CTA (8 warps x 16 for S-phase)
#define BK 64    // key rows per tile
#define NTILES (NSEQ / BK)

// Scratch (device globals)
__device__ float g_q[(size_t)BATCH * NSEQ * DKQ];    // [b][n][64], fp32, scaled log2e/8
__device__ float g_khi[(size_t)BATCH * NSEQ * DKQ];  // [b][n][64], tf32 hi, column-interleaved
__device__ float g_klo[(size_t)BATCH * NSEQ * DKQ];  // [b][n][64], tf32 lo, column-interleaved
__device__ float g_v[(size_t)BATCH * NSEQ * DOUT];   // [b][n][256], tf32-truncated

__device__ __forceinline__ float tf32_hi(float x) {
    return __uint_as_float(__float_as_uint(x) & 0xFFFFE000u);
}
__device__ __forceinline__ float fast_exp2(float x) {
    float r;
    asm("ex2.approx.ftz.f32 %0, %1;" : "=f"(r) : "f"(x));
    return r;
}

// packed f32x2 helpers for projection
__device__ __forceinline__ unsigned long long pack2(float a, float b) {
    unsigned long long r;
    asm("mov.b64 %0, {%1, %2};" : "=l"(r) : "f"(a), "f"(b));
    return r;
}
__device__ __forceinline__ void ffma2(unsigned long long& acc,
                                      unsigned long long a, unsigned long long b) {
    asm("fma.rn.f32x2 %0, %1, %2, %3;" : "=l"(acc) : "l"(a), "l"(b), "l"(acc));
}
__device__ __forceinline__ float2 unpack2(unsigned long long v) {
    float2 r;
    asm("mov.b64 {%0, %1}, %2;" : "=f"(r.x), "=f"(r.y) : "l"(v));
    return r;
}

// m16n8k8 tf32 mma: D += A x B (row.col), accum fp32
__device__ __forceinline__ void mma8(float4& d,
                                     uint32_t a0, uint32_t a1, uint32_t a2, uint32_t a3,
                                     uint32_t b0, uint32_t b1) {
    asm("mma.sync.aligned.m16n8k8.row.col.f32.tf32.tf32.f32 "
        "{%0,%1,%2,%3}, {%4,%5,%6,%7}, {%8,%9}, {%0,%1,%2,%3};"
        : "+f"(d.x), "+f"(d.y), "+f"(d.z), "+f"(d.w)
        : "r"(a0), "r"(a1), "r"(a2), "r"(a3), "r"(b0), "r"(b1));
}

// ==================== projection kernel ====================
__global__ __launch_bounds__(256) void proj_kernel(const float* __restrict__ x,
                                                   const float* __restrict__ Wq,
                                                   const float* __restrict__ Wk,
                                                   const float* __restrict__ Wv) {
    const int n0    = blockIdx.x * 64;
    const int jtile = blockIdx.y;      // 0:q  1:k  2..5:v chunks
    const int b     = blockIdx.z;

    const float* W;
    int j0;
    float scale;
    if (jtile == 0)      { W = Wq; j0 = 0;            scale = 0.125f * 1.4426950408889634f; }
    else if (jtile == 1) { W = Wk; j0 = 0;            scale = 1.0f; }
    else                 { W = Wv; j0 = (jtile-2)*64; scale = 1.0f; }

    __shared__ float xs[16][64];
    __shared__ float wt[16][64];

    const int t  = threadIdx.x;
    const int tn = t >> 4;
    const int tj = t & 15;

    unsigned long long acc2[4][2];
    #pragma unroll
    for (int i = 0; i < 4; i++) { acc2[i][0] = 0ull; acc2[i][1] = 0ull; }

    for (int c0 = 0; c0 < CIN; c0 += 16) {
        {
            int cc = t >> 4;
            int nn = (t & 15) * 4;
            float4 xv = *(const float4*)&x[((size_t)(b * CIN + c0 + cc)) * NSEQ + n0 + nn];
            *(float4*)&xs[cc][nn] = xv;
        }
        {
            int jj = t >> 2;
            int cp = (t & 3) * 4;
            float4 wv = *(const float4*)&W[(size_t)(j0 + jj) * CIN + c0 + cp];
            wt[cp + 0][jj] = wv.x;
            wt[cp + 1][jj] = wv.y;
            wt[cp + 2][jj] = wv.z;
            wt[cp + 3][jj] = wv.w;
        }
        __syncthreads();
        #pragma unroll
        for (int c = 0; c < 16; c++) {
            ulonglong2 b2 = *(const ulonglong2*)&wt[c][4 * tj];
            #pragma unroll
            for (int i = 0; i < 4; i++) {
                float a = xs[c][4 * tn + i];
                unsigned long long aa = pack2(a, a);
                ffma2(acc2[i][0], aa, b2.x);
                ffma2(acc2[i][1], aa, b2.y);
            }
        }
        __syncthreads();
    }

    if (jtile == 1) {
        // K: hi/lo split, column-interleaved: col c -> (c&3)*2 + ((c>>2)&1) + (c>>3)*8
        // This thread's cols c = 4*tj + i2 -> pos = 2*i2 + (tj&1) + 8*(tj>>1)
        const int pbase = (tj & 1) + 8 * (tj >> 1);
        #pragma unroll
        for (int i = 0; i < 4; i++) {
            int n = n0 + 4 * tn + i;
            size_t base = ((size_t)b * NSEQ + n) * DKQ;
            float2 lo2 = unpack2(acc2[i][0]);
            float2 hi2 = unpack2(acc2[i][1]);
            float vv[4] = { lo2.x, lo2.y, hi2.x, hi2.y };
            #pragma unroll
            for (int i2 = 0; i2 < 4; i2++) {
                float h = tf32_hi(vv[i2]);
                float l = tf32_hi(vv[i2] - h);
                g_khi[base + pbase + 2 * i2] = h;
                g_klo[base + pbase + 2 * i2] = l;
            }
        }
    } else {
        float* outp = (jtile == 0) ? g_q : g_v;
        int odim = (jtile >= 2) ? DOUT : DKQ;
        bool trunc = (jtile >= 2);
        #pragma unroll
        for (int i = 0; i < 4; i++) {
            int n = n0 + 4 * tn + i;
            size_t base = ((size_t)b * NSEQ + n) * odim + j0 + 4 * tj;
            float2 lo2 = unpack2(acc2[i][0]);
            float2 hi2 = unpack2(acc2[i][1]);
            float4 v = make_float4(lo2.x * scale, lo2.y * scale, hi2.x * scale, hi2.y * scale);
            if (trunc) v = make_float4(tf32_hi(v.x), tf32_hi(v.y), tf32_hi(v.z), tf32_hi(v.w));
            *(float4*)&outp[base] = v;
        }
    }
}

// ==================== mma.sync flash attention, role-split PV ====================
// 256 threads = 8 warps.
//  S-phase:  warp w owns query rows [w*16, w*16+16).
//  PV-phase: warp w = (rg = w>>1, cg = w&1): rows [32rg, 32rg+32) x channels [128cg, 128cg+128).
// SMEM (floats):
//  sKh [64][72] @0, sKl [64][72] @4608  (column-interleaved, direct copy from gmem)
//  sV  [32][520] @9216  (k-pair interleaved: pos = 2n + (k&4?1:0), rp = ((k>>3)<<2)+(k&3))
//  sP  [128][68] @25856 (plain row-major; doubles as Q staging in prologue)
//  lrow[128] @34560
#define KH_O 0
#define KL_O 4608
#define V_O  9216
#define P_O  25856
#define L_O  34560
#define SMEM_FLOATS 34688   // 138752 bytes

__global__ __launch_bounds__(256, 1) void attn_mma(float* __restrict__ out) {
    extern __shared__ float sm[];
    float* sKh = sm + KH_O;
    float* sKl = sm + KL_O;
    float* sV  = sm + V_O;
    float* sP  = sm + P_O;
    float* lrow = sm + L_O;
    const uint32_t* sPu = (const uint32_t*)sP;

    const int tid = threadIdx.x;
    const int w   = tid >> 5;
    const int ln  = tid & 31;
    const int l4  = ln >> 2;   // 0..7
    const int lm4 = ln & 3;    // 0..3
    const int rg  = w >> 1;    // 0..3 (PV row-group)
    const int cg  = w & 1;     // 0..1 (PV channel-group)
    const int b   = blockIdx.y;
    const int n0  = blockIdx.x * BM;

    // ---- stage Q through sP, build per-lane Qh/Ql fragments in registers ----
    uint32_t qh0[8], qh1[8], qh2[8], qh3[8];
    uint32_t ql0[8], ql1[8], ql2[8], ql3[8];
    {
        const float* qg = g_q + ((size_t)b * NSEQ + n0) * DKQ;
        #pragma unroll
        for (int it = 0; it < 8; it++) {
            int i = tid + it * 256;
            int r = i >> 4, c4 = i & 15;
            *(float4*)&sP[r * 68 + 4 * c4] = *(const float4*)&qg[(size_t)r * DKQ + 4 * c4];
        }
        __syncthreads();
        const int r0 = (w * 16 + l4) * 68;
        const int r1 = r0 + 8 * 68;
        #pragma unroll
        for (int kt = 0; kt < 8; kt++) {
            int c0 = kt * 8 + lm4;
            float v00 = sP[r0 + c0],     v10 = sP[r1 + c0];
            float v01 = sP[r0 + c0 + 4], v11 = sP[r1 + c0 + 4];
            float h00 = tf32_hi(v00), h10 = tf32_hi(v10);
            float h01 = tf32_hi(v01), h11 = tf32_hi(v11);
            qh0[kt] = __float_as_uint(h00); qh1[kt] = __float_as_uint(h10);
            qh2[kt] = __float_as_uint(h01); qh3[kt] = __float_as_uint(h11);
            ql0[kt] = __float_as_uint(tf32_hi(v00 - h00));
            ql1[kt] = __float_as_uint(tf32_hi(v10 - h10));
            ql2[kt] = __float_as_uint(tf32_hi(v01 - h01));
            ql3[kt] = __float_as_uint(tf32_hi(v11 - h11));
        }
    }

    float4 O[32];   // [mb*16 + nt]: rows 32rg+16mb+{l4,l4+8}, ch 128cg + nt*8 + 2lm4(+1)
    #pragma unroll
    for (int nt = 0; nt < 32; nt++) O[nt] = make_float4(0.f, 0.f, 0.f, 0.f);
    float lsumA = 0.f, lsumB = 0.f;

    const int prow = (w * 16 + l4) * 68;

    #pragma unroll 1
    for (int t = 0; t < NTILES; t++) {
        const int k0 = t * BK;
        __syncthreads();   // all warps done with prev tile's sK/sV/sP

        // ---- K tile: raw copy (pre-split, pre-interleaved in gmem) ----
        {
            #pragma unroll
            for (int it = 0; it < 8; it++) {
                int i = tid + it * 256;          // 2048 tasks: 2 arrays x 64 rows x 16 f4
                int arr = i >> 10, r = (i >> 4) & 63, c4 = i & 15;
                const float* src = (arr ? g_klo : g_khi) +
                                   ((size_t)b * NSEQ + k0 + r) * DKQ + 4 * c4;
                float* dst = (arr ? sKl : sKh) + r * 72 + 4 * c4;
                *(float4*)dst = *(const float4*)src;
            }
        }
        // ---- V tile: k-pair interleave (already tf32 in gmem) ----
        {
            const float* vg = g_v + ((size_t)b * NSEQ + k0) * DOUT;
            #pragma unroll
            for (int it = 0; it < 16; it++) {
                int i = tid + it * 256;          // 4096 tasks: 32 row-pairs x 128 n-pairs
                int np = i & 127, rp = i >> 7;
                int k = ((rp >> 2) << 3) + (rp & 3);
                float2 A = *(const float2*)&vg[(size_t)k * DOUT + 2 * np];
                float2 B = *(const float2*)&vg[(size_t)(k + 4) * DOUT + 2 * np];
                *(float4*)&sV[rp * 520 + 4 * np] = make_float4(A.x, B.x, A.y, B.y);
            }
        }
        __syncthreads();

        // ---- S = Qhi*(Khi+Klo) + Qlo*Khi  (3-pass tf32); rows w*16..+15 ----
        float4 S[8];
        #pragma unroll
        for (int nt = 0; nt < 8; nt++) S[nt] = make_float4(0.f, 0.f, 0.f, 0.f);

        #pragma unroll
        for (int kt = 0; kt < 8; kt++) {
            #pragma unroll
            for (int nt = 0; nt < 8; nt++) {
                const int bc = (nt * 8 + l4) * 72 + kt * 8 + lm4 * 2;
                float2 kh = *(const float2*)&sKh[bc];
                float2 kl = *(const float2*)&sKl[bc];
                uint32_t khx = __float_as_uint(kh.x), khy = __float_as_uint(kh.y);
                mma8(S[nt], qh0[kt], qh1[kt], qh2[kt], qh3[kt], khx, khy);
                mma8(S[nt], qh0[kt], qh1[kt], qh2[kt], qh3[kt],
                     __float_as_uint(kl.x), __float_as_uint(kl.y));
                mma8(S[nt], ql0[kt], ql1[kt], ql2[kt], ql3[kt], khx, khy);
            }
        }

        // ---- softmax (log2 domain, no max subtraction); P truncated, lsum from p-hat ----
        #pragma unroll
        for (int nt = 0; nt < 8; nt++) {
            float p0 = tf32_hi(fast_exp2(S[nt].x));
            float p1 = tf32_hi(fast_exp2(S[nt].y));
            float p2 = tf32_hi(fast_exp2(S[nt].z));
            float p3 = tf32_hi(fast_exp2(S[nt].w));
            lsumA += p0 + p1;
            lsumB += p2 + p3;
            const int pc = prow + nt * 8 + 2 * lm4;
            *(float2*)&sP[pc]          = make_float2(p0, p1);
            *(float2*)&sP[pc + 8 * 68] = make_float2(p2, p3);
        }
        __syncthreads();   // P visible block-wide for role-split PV

        // ---- O += P * V : rows [32rg,32rg+32) x channels [128cg,128cg+128) ----
        #pragma unroll 1
        for (int kt = 0; kt < 8; kt++) {
            // V fragments for this kt (reused across both mb blocks)
            const int vb = (kt * 4 + lm4) * 520 + 2 * l4 + cg * 256;
            #pragma unroll
            for (int mb = 0; mb < 2; mb++) {
                const int ac = (32 * rg + 16 * mb + l4) * 68 + kt * 8 + lm4;
                uint32_t p0 = sPu[ac],     p1 = sPu[ac + 8 * 68];
                uint32_t p2 = sPu[ac + 4], p3 = sPu[ac + 8 * 68 + 4];
                #pragma unroll
                for (int nt = 0; nt < 16; nt++) {
                    float2 v2 = *(const float2*)&sV[vb + nt * 16];
                    mma8(O[mb * 16 + nt], p0, p1, p2, p3,
                         __float_as_uint(v2.x), __float_as_uint(v2.y));
                }
            }
        }
    }

    // ---- epilogue: broadcast lsum, normalize, write ----
    lsumA += __shfl_xor_sync(0xffffffffu, lsumA, 1);
    lsumA += __shfl_xor_sync(0xffffffffu, lsumA, 2);
    lsumB += __shfl_xor_sync(0xffffffffu, lsumB, 1);
    lsumB += __shfl_xor_sync(0xffffffffu, lsumB, 2);
    if (lm4 == 0) {
        lrow[w * 16 + l4]     = lsumA;
        lrow[w * 16 + l4 + 8] = lsumB;
    }
    __syncthreads();

    #pragma unroll
    for (int mb = 0; mb < 2; mb++) {
        const int rbase = 32 * rg + 16 * mb + l4;
        float invA = 1.0f / lrow[rbase];
        float invB = 1.0f / lrow[rbase + 8];
        float* ob = out + (size_t)b * DOUT * NSEQ + n0 + rbase;
        #pragma unroll
        for (int nt = 0; nt < 16; nt++) {
            int o = 128 * cg + nt * 8 + 2 * lm4;
            float4 v = O[mb * 16 + nt];
            ob[(size_t)o * NSEQ]           = v.x * invA;
            ob[(size_t)(o + 1) * NSEQ]     = v.y * invA;
            ob[(size_t)o * NSEQ + 8]       = v.z * invB;
            ob[(size_t)(o + 1) * NSEQ + 8] = v.w * invB;
        }
    }
}

extern "C" void kernel_launch(void* const* d_in, const int* in_sizes, int n_in,
                              void* d_out, int out_size) {
    (void)in_sizes; (void)n_in; (void)out_size;
    const float* x  = (const float*)d_in[0];
    const float* Wq = (const float*)d_in[1];
    const float* Wk = (const float*)d_in[2];
    const float* Wv = (const float*)d_in[3];
    float* out = (float*)d_out;

    cudaFuncSetAttribute(attn_mma, cudaFuncAttributeMaxDynamicSharedMemorySize,
                         SMEM_FLOATS * (int)sizeof(float));

    dim3 gp(NSEQ / 64, 6, BATCH);
    proj_kernel<<<gp, 256>>>(x, Wq, Wk, Wv);

    dim3 ga(NSEQ / BM, BATCH);
    attn_mma<<<ga, 256, SMEM_FLOATS * sizeof(float)>>>(out);
}

// round 10
// speedup vs baseline: 1.3361x; 1.0863x over previous
#include <cuda_runtime.h>
#include <math.h>
#include <stdint.h>

// Problem constants
#define BATCH 8
#define CIN   256
#define NSEQ  4096
#define DKQ   64
#define DOUT  256

// Attention tiling
#define BM 128   // query rows per CTA (8 warps x 16 for S-phase)
#define BK 64    // key rows per tile
#define NTILES (NSEQ / BK)

// Scratch (device globals)
__device__ float g_q[(size_t)BATCH * NSEQ * DKQ];    // [b][n][64], fp32, scaled log2e/8
__device__ float g_khi[(size_t)BATCH * NSEQ * DKQ];  // [b][n][64], tf32 hi, column-interleaved
__device__ float g_klo[(size_t)BATCH * NSEQ * DKQ];  // [b][n][64], tf32 lo, column-interleaved
__device__ float g_v[(size_t)BATCH * NSEQ * DOUT];   // [b][n][256], tf32-truncated

__device__ __forceinline__ float tf32_hi(float x) {
    return __uint_as_float(__float_as_uint(x) & 0xFFFFE000u);
}
__device__ __forceinline__ float fast_exp2(float x) {
    float r;
    asm("ex2.approx.ftz.f32 %0, %1;" : "=f"(r) : "f"(x));
    return r;
}
__device__ __forceinline__ uint32_t smem_u32(const void* p) {
    uint32_t a;
    asm("{ .reg .u64 t; cvta.to.shared.u64 t, %1; cvt.u32.u64 %0, t; }" : "=r"(a) : "l"(p));
    return a;
}
__device__ __forceinline__ void cp_async16(uint32_t dst, const void* src) {
    asm volatile("cp.async.cg.shared.global [%0], [%1], 16;" :: "r"(dst), "l"(src));
}
#define CP_COMMIT() asm volatile("cp.async.commit_group;" ::: "memory")
#define CP_WAIT(N)  asm volatile("cp.async.wait_group %0;" :: "n"(N) : "memory")

// packed f32x2 helpers for projection
__device__ __forceinline__ unsigned long long pack2(float a, float b) {
    unsigned long long r;
    asm("mov.b64 %0, {%1, %2};" : "=l"(r) : "f"(a), "f"(b));
    return r;
}
__device__ __forceinline__ void ffma2(unsigned long long& acc,
                                      unsigned long long a, unsigned long long b) {
    asm("fma.rn.f32x2 %0, %1, %2, %3;" : "=l"(acc) : "l"(a), "l"(b), "l"(acc));
}
__device__ __forceinline__ float2 unpack2(unsigned long long v) {
    float2 r;
    asm("mov.b64 {%0, %1}, %2;" : "=f"(r.x), "=f"(r.y) : "l"(v));
    return r;
}

// m16n8k8 tf32 mma: D += A x B (row.col), accum fp32
__device__ __forceinline__ void mma8(float4& d,
                                     uint32_t a0, uint32_t a1, uint32_t a2, uint32_t a3,
                                     uint32_t b0, uint32_t b1) {
    asm("mma.sync.aligned.m16n8k8.row.col.f32.tf32.tf32.f32 "
        "{%0,%1,%2,%3}, {%4,%5,%6,%7}, {%8,%9}, {%0,%1,%2,%3};"
        : "+f"(d.x), "+f"(d.y), "+f"(d.z), "+f"(d.w)
        : "r"(a0), "r"(a1), "r"(a2), "r"(a3), "r"(b0), "r"(b1));
}

// ==================== projection kernel ====================
__global__ __launch_bounds__(256) void proj_kernel(const float* __restrict__ x,
                                                   const float* __restrict__ Wq,
                                                   const float* __restrict__ Wk,
                                                   const float* __restrict__ Wv) {
    const int n0    = blockIdx.x * 64;
    const int jtile = blockIdx.y;      // 0:q  1:k  2..5:v chunks
    const int b     = blockIdx.z;

    const float* W;
    int j0;
    float scale;
    if (jtile == 0)      { W = Wq; j0 = 0;            scale = 0.125f * 1.4426950408889634f; }
    else if (jtile == 1) { W = Wk; j0 = 0;            scale = 1.0f; }
    else                 { W = Wv; j0 = (jtile-2)*64; scale = 1.0f; }

    __shared__ float xs[16][64];
    __shared__ float wt[16][64];

    const int t  = threadIdx.x;
    const int tn = t >> 4;
    const int tj = t & 15;

    unsigned long long acc2[4][2];
    #pragma unroll
    for (int i = 0; i < 4; i++) { acc2[i][0] = 0ull; acc2[i][1] = 0ull; }

    for (int c0 = 0; c0 < CIN; c0 += 16) {
        {
            int cc = t >> 4;
            int nn = (t & 15) * 4;
            float4 xv = *(const float4*)&x[((size_t)(b * CIN + c0 + cc)) * NSEQ + n0 + nn];
            *(float4*)&xs[cc][nn] = xv;
        }
        {
            int jj = t >> 2;
            int cp = (t & 3) * 4;
            float4 wv = *(const float4*)&W[(size_t)(j0 + jj) * CIN + c0 + cp];
            wt[cp + 0][jj] = wv.x;
            wt[cp + 1][jj] = wv.y;
            wt[cp + 2][jj] = wv.z;
            wt[cp + 3][jj] = wv.w;
        }
        __syncthreads();
        #pragma unroll
        for (int c = 0; c < 16; c++) {
            ulonglong2 b2 = *(const ulonglong2*)&wt[c][4 * tj];
            #pragma unroll
            for (int i = 0; i < 4; i++) {
                float a = xs[c][4 * tn + i];
                unsigned long long aa = pack2(a, a);
                ffma2(acc2[i][0], aa, b2.x);
                ffma2(acc2[i][1], aa, b2.y);
            }
        }
        __syncthreads();
    }

    if (jtile == 1) {
        // K: hi/lo split, column-interleaved: col c -> (c&3)*2 + ((c>>2)&1) + (c>>3)*8
        const int pbase = (tj & 1) + 8 * (tj >> 1);
        #pragma unroll
        for (int i = 0; i < 4; i++) {
            int n = n0 + 4 * tn + i;
            size_t base = ((size_t)b * NSEQ + n) * DKQ;
            float2 lo2 = unpack2(acc2[i][0]);
            float2 hi2 = unpack2(acc2[i][1]);
            float vv[4] = { lo2.x, lo2.y, hi2.x, hi2.y };
            #pragma unroll
            for (int i2 = 0; i2 < 4; i2++) {
                float h = tf32_hi(vv[i2]);
                float l = tf32_hi(vv[i2] - h);
                g_khi[base + pbase + 2 * i2] = h;
                g_klo[base + pbase + 2 * i2] = l;
            }
        }
    } else {
        float* outp = (jtile == 0) ? g_q : g_v;
        int odim = (jtile >= 2) ? DOUT : DKQ;
        bool trunc = (jtile >= 2);
        #pragma unroll
        for (int i = 0; i < 4; i++) {
            int n = n0 + 4 * tn + i;
            size_t base = ((size_t)b * NSEQ + n) * odim + j0 + 4 * tj;
            float2 lo2 = unpack2(acc2[i][0]);
            float2 hi2 = unpack2(acc2[i][1]);
            float4 v = make_float4(lo2.x * scale, lo2.y * scale, hi2.x * scale, hi2.y * scale);
            if (trunc) v = make_float4(tf32_hi(v.x), tf32_hi(v.y), tf32_hi(v.z), tf32_hi(v.w));
            *(float4*)&outp[base] = v;
        }
    }
}

// ==================== cp.async pipelined flash attention ====================
// 256 threads = 8 warps. Single-buffered K and V, pipelined via disjoint consumers:
//   QK reads only K;  PV reads only V+P.
//   K(t+1) streams in during PV(t); V(t+1) streams in during QK(t+1)+softmax.
// SMEM (floats):
//  sKh [64][72] @0, sKl [64][72] @4608  (column-interleaved, raw copy from gmem)
//  sV  [64][264] @9216  (plain row-major, raw copy)
//  sP  [128][68] @26112 (row-major; doubles as Q staging in prologue)
//  lrow[128] @34816
#define KH_O 0
#define KL_O 4608
#define V_O  9216
#define P_O  26112
#define L_O  34816
#define SMEM_FLOATS 34944   // 139776 bytes

// cp.async issue helpers (each thread copies its slice; 16B chunks)
__device__ __forceinline__ void issue_k(int b, int k0, int tid, uint32_t smb) {
    #pragma unroll
    for (int it = 0; it < 8; it++) {
        int i = tid + it * 256;              // 2048 chunks: 2 arrays x 64 rows x 16
        int arr = i >> 10, r = (i >> 4) & 63, c4 = i & 15;
        const float* src = (arr ? g_klo : g_khi) +
                           ((size_t)b * NSEQ + k0 + r) * DKQ + 4 * c4;
        uint32_t dst = smb + (uint32_t)(arr ? KL_O : KH_O) * 4 + r * 288 + c4 * 16;
        cp_async16(dst, src);
    }
}
__device__ __forceinline__ void issue_v(int b, int k0, int tid, uint32_t smb) {
    const float* vg = g_v + ((size_t)b * NSEQ + k0) * DOUT;
    #pragma unroll
    for (int it = 0; it < 16; it++) {
        int i = tid + it * 256;              // 4096 chunks: 64 rows x 64
        int r = i >> 6, c4 = i & 63;
        uint32_t dst = smb + (uint32_t)V_O * 4 + r * 1056 + c4 * 16;
        cp_async16(dst, vg + (size_t)r * DOUT + 4 * c4);
    }
}

__global__ __launch_bounds__(256, 1) void attn_mma(float* __restrict__ out) {
    extern __shared__ float sm[];
    float* sKh = sm + KH_O;
    float* sKl = sm + KL_O;
    float* sV  = sm + V_O;
    float* sP  = sm + P_O;
    float* lrow = sm + L_O;
    const uint32_t* sPu = (const uint32_t*)sP;
    const uint32_t smb = smem_u32(sm);

    const int tid = threadIdx.x;
    const int w   = tid >> 5;
    const int ln  = tid & 31;
    const int l4  = ln >> 2;   // 0..7
    const int lm4 = ln & 3;    // 0..3
    const int rg  = w >> 1;    // 0..3 (PV row-group)
    const int cg  = w & 1;     // 0..1 (PV channel-group)
    const int b   = blockIdx.y;
    const int n0  = blockIdx.x * BM;

    // ---- start the pipeline: K(0), V(0) in flight during Q staging ----
    issue_k(b, 0, tid, smb);
    CP_COMMIT();
    issue_v(b, 0, tid, smb);
    CP_COMMIT();

    // ---- stage Q through sP, build per-lane Qh/Ql fragments in registers ----
    uint32_t qh0[8], qh1[8], qh2[8], qh3[8];
    uint32_t ql0[8], ql1[8], ql2[8], ql3[8];
    {
        const float* qg = g_q + ((size_t)b * NSEQ + n0) * DKQ;
        #pragma unroll
        for (int it = 0; it < 8; it++) {
            int i = tid + it * 256;
            int r = i >> 4, c4 = i & 15;
            *(float4*)&sP[r * 68 + 4 * c4] = *(const float4*)&qg[(size_t)r * DKQ + 4 * c4];
        }
        __syncthreads();
        const int r0 = (w * 16 + l4) * 68;
        const int r1 = r0 + 8 * 68;
        #pragma unroll
        for (int kt = 0; kt < 8; kt++) {
            int c0 = kt * 8 + lm4;
            float v00 = sP[r0 + c0],     v10 = sP[r1 + c0];
            float v01 = sP[r0 + c0 + 4], v11 = sP[r1 + c0 + 4];
            float h00 = tf32_hi(v00), h10 = tf32_hi(v10);
            float h01 = tf32_hi(v01), h11 = tf32_hi(v11);
            qh0[kt] = __float_as_uint(h00); qh1[kt] = __float_as_uint(h10);
            qh2[kt] = __float_as_uint(h01); qh3[kt] = __float_as_uint(h11);
            ql0[kt] = __float_as_uint(tf32_hi(v00 - h00));
            ql1[kt] = __float_as_uint(tf32_hi(v10 - h10));
            ql2[kt] = __float_as_uint(tf32_hi(v01 - h01));
            ql3[kt] = __float_as_uint(tf32_hi(v11 - h11));
        }
    }

    float4 O[32];   // [mb*16+nt]: rows 32rg+16mb+{l4,l4+8}, ch 128cg + nt*8 + 2lm4(+1)
    #pragma unroll
    for (int nt = 0; nt < 32; nt++) O[nt] = make_float4(0.f, 0.f, 0.f, 0.f);
    float lsumA = 0.f, lsumB = 0.f;

    const int prow = (w * 16 + l4) * 68;

    #pragma unroll 1
    for (int t = 0; t < NTILES; t++) {
        // ---- K(t) ready (V(t) may still be in flight) ----
        CP_WAIT(1);
        __syncthreads();

        // ---- S = Qhi*(Khi+Klo) + Qlo*Khi  (3-pass tf32); rows w*16..+15 ----
        float4 S[8];
        #pragma unroll
        for (int nt = 0; nt < 8; nt++) S[nt] = make_float4(0.f, 0.f, 0.f, 0.f);

        #pragma unroll
        for (int kt = 0; kt < 8; kt++) {
            #pragma unroll
            for (int nt = 0; nt < 8; nt++) {
                const int bc = (nt * 8 + l4) * 72 + kt * 8 + lm4 * 2;
                float2 kh = *(const float2*)&sKh[bc];
                float2 kl = *(const float2*)&sKl[bc];
                uint32_t khx = __float_as_uint(kh.x), khy = __float_as_uint(kh.y);
                mma8(S[nt], qh0[kt], qh1[kt], qh2[kt], qh3[kt], khx, khy);
                mma8(S[nt], qh0[kt], qh1[kt], qh2[kt], qh3[kt],
                     __float_as_uint(kl.x), __float_as_uint(kl.y));
                mma8(S[nt], ql0[kt], ql1[kt], ql2[kt], ql3[kt], khx, khy);
            }
        }

        // ---- softmax (log2 domain); P tf32-truncated, lsum from p-hat ----
        #pragma unroll
        for (int nt = 0; nt < 8; nt++) {
            float p0 = tf32_hi(fast_exp2(S[nt].x));
            float p1 = tf32_hi(fast_exp2(S[nt].y));
            float p2 = tf32_hi(fast_exp2(S[nt].z));
            float p3 = tf32_hi(fast_exp2(S[nt].w));
            lsumA += p0 + p1;
            lsumB += p2 + p3;
            const int pc = prow + nt * 8 + 2 * lm4;
            *(float2*)&sP[pc]          = make_float2(p0, p1);
            *(float2*)&sP[pc + 8 * 68] = make_float2(p2, p3);
        }
        __syncthreads();   // all QK reads of K done + P visible block-wide

        // ---- stream K(t+1) into the (now free) K buffer; overlaps PV ----
        if (t + 1 < NTILES) issue_k(b, (t + 1) * BK, tid, smb);
        CP_COMMIT();       // uniform group count (empty group on last tile)

        // ---- V(t) ready (K(t+1) still in flight) ----
        CP_WAIT(1);
        __syncthreads();

        // ---- O += P * V : rows [32rg,32rg+32) x channels [128cg,128cg+128) ----
        #pragma unroll 1
        for (int kt = 0; kt < 8; kt++) {
            // P fragments for both mb row-blocks (hoisted)
            const int ac0 = (32 * rg + l4) * 68 + kt * 8 + lm4;
            const int ac1 = ac0 + 16 * 68;
            uint32_t pa0 = sPu[ac0],     pa1 = sPu[ac0 + 8 * 68];
            uint32_t pa2 = sPu[ac0 + 4], pa3 = sPu[ac0 + 8 * 68 + 4];
            uint32_t pb0 = sPu[ac1],     pb1 = sPu[ac1 + 8 * 68];
            uint32_t pb2 = sPu[ac1 + 4], pb3 = sPu[ac1 + 8 * 68 + 4];
            const int v0b = (kt * 8 + lm4) * 264 + 128 * cg + l4;
            const int v1b = v0b + 4 * 264;
            #pragma unroll
            for (int nt = 0; nt < 16; nt++) {
                uint32_t v0 = __float_as_uint(sV[v0b + nt * 8]);
                uint32_t v1 = __float_as_uint(sV[v1b + nt * 8]);
                mma8(O[nt],      pa0, pa1, pa2, pa3, v0, v1);
                mma8(O[16 + nt], pb0, pb1, pb2, pb3, v0, v1);
            }
        }
        __syncthreads();   // all PV reads of V done

        // ---- stream V(t+1); overlaps next tile's QK + softmax ----
        if (t + 1 < NTILES) issue_v(b, (t + 1) * BK, tid, smb);
        CP_COMMIT();
    }

    // ---- epilogue: broadcast lsum, normalize, write ----
    lsumA += __shfl_xor_sync(0xffffffffu, lsumA, 1);
    lsumA += __shfl_xor_sync(0xffffffffu, lsumA, 2);
    lsumB += __shfl_xor_sync(0xffffffffu, lsumB, 1);
    lsumB += __shfl_xor_sync(0xffffffffu, lsumB, 2);
    if (lm4 == 0) {
        lrow[w * 16 + l4]     = lsumA;
        lrow[w * 16 + l4 + 8] = lsumB;
    }
    __syncthreads();

    #pragma unroll
    for (int mb = 0; mb < 2; mb++) {
        const int rbase = 32 * rg + 16 * mb + l4;
        float invA = 1.0f / lrow[rbase];
        float invB = 1.0f / lrow[rbase + 8];
        float* ob = out + (size_t)b * DOUT * NSEQ + n0 + rbase;
        #pragma unroll
        for (int nt = 0; nt < 16; nt++) {
            int o = 128 * cg + nt * 8 + 2 * lm4;
            float4 v = O[mb * 16 + nt];
            ob[(size_t)o * NSEQ]           = v.x * invA;
            ob[(size_t)(o + 1) * NSEQ]     = v.y * invA;
            ob[(size_t)o * NSEQ + 8]       = v.z * invB;
            ob[(size_t)(o + 1) * NSEQ + 8] = v.w * invB;
        }
    }
}

extern "C" void kernel_launch(void* const* d_in, const int* in_sizes, int n_in,
                              void* d_out, int out_size) {
    (void)in_sizes; (void)n_in; (void)out_size;
    const float* x  = (const float*)d_in[0];
    const float* Wq = (const float*)d_in[1];
    const float* Wk = (const float*)d_in[2];
    const float* Wv = (const float*)d_in[3];
    float* out = (float*)d_out;

    cudaFuncSetAttribute(attn_mma, cudaFuncAttributeMaxDynamicSharedMemorySize,
                         SMEM_FLOATS * (int)sizeof(float));

    dim3 gp(NSEQ / 64, 6, BATCH);
    proj_kernel<<<gp, 256>>>(x, Wq, Wk, Wv);

    dim3 ga(NSEQ / BM, BATCH);
    attn_mma<<<ga, 256, SMEM_FLOATS * sizeof(float)>>>(out);
}

// round 11
// speedup vs baseline: 1.6738x; 1.2527x over previous
#include <cuda_runtime.h>
#include <cuda_bf16.h>
#include <math.h>
#include <stdint.h>

// Problem constants
#define BATCH 8
#define CIN   256
#define NSEQ  4096
#define DKQ   64
#define DOUT  256

// Attention tiling
#define BM 128   // query rows per CTA (8 warps x 16 for S-phase)
#define BK 64    // key rows per tile
#define NTILES (NSEQ / BK)

// Scratch (device globals)
__device__ float    g_q[(size_t)BATCH * NSEQ * DKQ];    // [b][n][64], fp32, scaled log2e/8
__device__ uint32_t g_khi[(size_t)BATCH * NSEQ * 32];   // [b][n][32] bf16x2, hi, interleaved
__device__ uint32_t g_klo[(size_t)BATCH * NSEQ * 32];   // [b][n][32] bf16x2, lo, interleaved
__device__ float    g_v[(size_t)BATCH * NSEQ * DOUT];   // [b][n][256], tf32-truncated

__device__ __forceinline__ float tf32_hi(float x) {
    return __uint_as_float(__float_as_uint(x) & 0xFFFFE000u);
}
__device__ __forceinline__ float fast_exp2(float x) {
    float r;
    asm("ex2.approx.ftz.f32 %0, %1;" : "=f"(r) : "f"(x));
    return r;
}
__device__ __forceinline__ uint32_t smem_u32(const void* p) {
    uint32_t a;
    asm("{ .reg .u64 t; cvta.to.shared.u64 t, %1; cvt.u32.u64 %0, t; }" : "=r"(a) : "l"(p));
    return a;
}
__device__ __forceinline__ void cp_async16(uint32_t dst, const void* src) {
    asm volatile("cp.async.cg.shared.global [%0], [%1], 16;" :: "r"(dst), "l"(src));
}
#define CP_COMMIT() asm volatile("cp.async.commit_group;" ::: "memory")
#define CP_WAIT(N)  asm volatile("cp.async.wait_group %0;" :: "n"(N) : "memory")

// bf16 pack: returns u32 with lo element in low half, hi element in high half
__device__ __forceinline__ uint32_t packbf(float lo, float hi) {
    __nv_bfloat162 h2 = __floats2bfloat162_rn(lo, hi);
    return *(uint32_t*)&h2;
}
__device__ __forceinline__ float bf_lo_f(uint32_t p) { return __uint_as_float(p << 16); }
__device__ __forceinline__ float bf_hi_f(uint32_t p) { return __uint_as_float(p & 0xFFFF0000u); }

// packed f32x2 helpers for projection
__device__ __forceinline__ unsigned long long pack2(float a, float b) {
    unsigned long long r;
    asm("mov.b64 %0, {%1, %2};" : "=l"(r) : "f"(a), "f"(b));
    return r;
}
__device__ __forceinline__ void ffma2(unsigned long long& acc,
                                      unsigned long long a, unsigned long long b) {
    asm("fma.rn.f32x2 %0, %1, %2, %3;" : "=l"(acc) : "l"(a), "l"(b), "l"(acc));
}
__device__ __forceinline__ float2 unpack2(unsigned long long v) {
    float2 r;
    asm("mov.b64 {%0, %1}, %2;" : "=f"(r.x), "=f"(r.y) : "l"(v));
    return r;
}

// m16n8k8 tf32 mma (PV)
__device__ __forceinline__ void mma8(float4& d,
                                     uint32_t a0, uint32_t a1, uint32_t a2, uint32_t a3,
                                     uint32_t b0, uint32_t b1) {
    asm("mma.sync.aligned.m16n8k8.row.col.f32.tf32.tf32.f32 "
        "{%0,%1,%2,%3}, {%4,%5,%6,%7}, {%8,%9}, {%0,%1,%2,%3};"
        : "+f"(d.x), "+f"(d.y), "+f"(d.z), "+f"(d.w)
        : "r"(a0), "r"(a1), "r"(a2), "r"(a3), "r"(b0), "r"(b1));
}
// m16n8k16 bf16 mma (QK)
__device__ __forceinline__ void mma16bf(float4& d,
                                        uint32_t a0, uint32_t a1, uint32_t a2, uint32_t a3,
                                        uint32_t b0, uint32_t b1) {
    asm("mma.sync.aligned.m16n8k16.row.col.f32.bf16.bf16.f32 "
        "{%0,%1,%2,%3}, {%4,%5,%6,%7}, {%8,%9}, {%0,%1,%2,%3};"
        : "+f"(d.x), "+f"(d.y), "+f"(d.z), "+f"(d.w)
        : "r"(a0), "r"(a1), "r"(a2), "r"(a3), "r"(b0), "r"(b1));
}

// ==================== projection kernel ====================
__global__ __launch_bounds__(256) void proj_kernel(const float* __restrict__ x,
                                                   const float* __restrict__ Wq,
                                                   const float* __restrict__ Wk,
                                                   const float* __restrict__ Wv) {
    const int n0    = blockIdx.x * 64;
    const int jtile = blockIdx.y;      // 0:q  1:k  2..5:v chunks
    const int b     = blockIdx.z;

    const float* W;
    int j0;
    float scale;
    if (jtile == 0)      { W = Wq; j0 = 0;            scale = 0.125f * 1.4426950408889634f; }
    else if (jtile == 1) { W = Wk; j0 = 0;            scale = 1.0f; }
    else                 { W = Wv; j0 = (jtile-2)*64; scale = 1.0f; }

    __shared__ float xs[16][64];
    __shared__ float wt[16][64];

    const int t  = threadIdx.x;
    const int tn = t >> 4;
    const int tj = t & 15;

    unsigned long long acc2[4][2];
    #pragma unroll
    for (int i = 0; i < 4; i++) { acc2[i][0] = 0ull; acc2[i][1] = 0ull; }

    for (int c0 = 0; c0 < CIN; c0 += 16) {
        {
            int cc = t >> 4;
            int nn = (t & 15) * 4;
            float4 xv = *(const float4*)&x[((size_t)(b * CIN + c0 + cc)) * NSEQ + n0 + nn];
            *(float4*)&xs[cc][nn] = xv;
        }
        {
            int jj = t >> 2;
            int cp = (t & 3) * 4;
            float4 wv = *(const float4*)&W[(size_t)(j0 + jj) * CIN + c0 + cp];
            wt[cp + 0][jj] = wv.x;
            wt[cp + 1][jj] = wv.y;
            wt[cp + 2][jj] = wv.z;
            wt[cp + 3][jj] = wv.w;
        }
        __syncthreads();
        #pragma unroll
        for (int c = 0; c < 16; c++) {
            ulonglong2 b2 = *(const ulonglong2*)&wt[c][4 * tj];
            #pragma unroll
            for (int i = 0; i < 4; i++) {
                float a = xs[c][4 * tn + i];
                unsigned long long aa = pack2(a, a);
                ffma2(acc2[i][0], aa, b2.x);
                ffma2(acc2[i][1], aa, b2.y);
            }
        }
        __syncthreads();
    }

    if (jtile == 1) {
        // K: bf16 hi/lo split, packed bf16x2 per u32 (features 2c,2c+1), interleaved:
        //   pos(c) = (c>>3)*8 + (c&3)*2 + ((c>>2)&1)
        // This thread owns u32 cols c = 2tj, 2tj+1.
        const int c0i = 2 * tj;
        const int pos0 = ((c0i >> 3) << 3) + ((c0i & 3) << 1) + ((c0i >> 2) & 1);
        const int c1i = 2 * tj + 1;
        const int pos1 = ((c1i >> 3) << 3) + ((c1i & 3) << 1) + ((c1i >> 2) & 1);
        #pragma unroll
        for (int i = 0; i < 4; i++) {
            int n = n0 + 4 * tn + i;
            size_t base = ((size_t)b * NSEQ + n) * 32;
            float2 lo2 = unpack2(acc2[i][0]);
            float2 hi2 = unpack2(acc2[i][1]);
            // features: 4tj..4tj+3 = (lo2.x, lo2.y, hi2.x, hi2.y)
            uint32_t h0 = packbf(lo2.x, lo2.y);
            uint32_t h1 = packbf(hi2.x, hi2.y);
            uint32_t l0 = packbf(lo2.x - bf_lo_f(h0), lo2.y - bf_hi_f(h0));
            uint32_t l1 = packbf(hi2.x - bf_lo_f(h1), hi2.y - bf_hi_f(h1));
            g_khi[base + pos0] = h0;
            g_khi[base + pos1] = h1;
            g_klo[base + pos0] = l0;
            g_klo[base + pos1] = l1;
        }
    } else {
        float* outp = (jtile == 0) ? g_q : g_v;
        int odim = (jtile >= 2) ? DOUT : DKQ;
        bool trunc = (jtile >= 2);
        #pragma unroll
        for (int i = 0; i < 4; i++) {
            int n = n0 + 4 * tn + i;
            size_t base = ((size_t)b * NSEQ + n) * odim + j0 + 4 * tj;
            float2 lo2 = unpack2(acc2[i][0]);
            float2 hi2 = unpack2(acc2[i][1]);
            float4 v = make_float4(lo2.x * scale, lo2.y * scale, hi2.x * scale, hi2.y * scale);
            if (trunc) v = make_float4(tf32_hi(v.x), tf32_hi(v.y), tf32_hi(v.z), tf32_hi(v.w));
            *(float4*)&outp[base] = v;
        }
    }
}

// ==================== cp.async pipelined flash attention (bf16 QK) ====================
// 256 threads = 8 warps. Single-buffered K and V, disjoint consumers:
//   QK reads only K (bf16);  PV reads only V+P (tf32).
// SMEM layout (float/u32 units):
//  sKh u32[64][40] @0 (2560), sKl @2560 (2560)   -- row stride 40 u32 (bank-clean for frags)
//  sV  f32[64][264] @5120 (16896)
//  sP  f32[128][68] @22016 (8704; Q staging in prologue)
//  lrow[128] @30720
#define KH_O 0
#define KL_O 2560
#define V_O  5120
#define P_O  22016
#define L_O  30720
#define SMEM_FLOATS 30848   // 123392 bytes

__device__ __forceinline__ void issue_k(int b, int k0, int tid, uint32_t smb) {
    #pragma unroll
    for (int it = 0; it < 4; it++) {
        int i = tid + it * 256;              // 1024 chunks: 2 arrays x 64 rows x 8
        int arr = i >> 9, r = (i >> 3) & 63, c = i & 7;
        const uint32_t* src = (arr ? g_klo : g_khi) +
                              ((size_t)b * NSEQ + k0 + r) * 32 + c * 4;
        uint32_t dst = smb + (uint32_t)(arr ? KL_O : KH_O) * 4 + r * 160 + c * 16;
        cp_async16(dst, src);
    }
}
__device__ __forceinline__ void issue_v(int b, int k0, int tid, uint32_t smb) {
    const float* vg = g_v + ((size_t)b * NSEQ + k0) * DOUT;
    #pragma unroll
    for (int it = 0; it < 16; it++) {
        int i = tid + it * 256;              // 4096 chunks: 64 rows x 64
        int r = i >> 6, c4 = i & 63;
        uint32_t dst = smb + (uint32_t)V_O * 4 + r * 1056 + c4 * 16;
        cp_async16(dst, vg + (size_t)r * DOUT + 4 * c4);
    }
}

__global__ __launch_bounds__(256, 1) void attn_mma(float* __restrict__ out) {
    extern __shared__ float sm[];
    const uint32_t* sKh = (const uint32_t*)sm + KH_O;
    const uint32_t* sKl = (const uint32_t*)sm + KL_O;
    float* sV  = sm + V_O;
    float* sP  = sm + P_O;
    float* lrow = sm + L_O;
    const uint32_t* sPu = (const uint32_t*)sP;
    const uint32_t smb = smem_u32(sm);

    const int tid = threadIdx.x;
    const int w   = tid >> 5;
    const int ln  = tid & 31;
    const int l4  = ln >> 2;   // 0..7
    const int lm4 = ln & 3;    // 0..3
    const int rg  = w >> 1;    // 0..3 (PV row-group)
    const int cg  = w & 1;     // 0..1 (PV channel-group)
    const int b   = blockIdx.y;
    const int n0  = blockIdx.x * BM;

    // ---- start the pipeline: K(0), V(0) in flight during Q staging ----
    issue_k(b, 0, tid, smb);
    CP_COMMIT();
    issue_v(b, 0, tid, smb);
    CP_COMMIT();

    // ---- stage Q through sP, build bf16 hi/lo A-fragments in registers ----
    // per kt (0..3): a0 = rows r0, feats (16kt+2lm4, +1); a1 = row r1; a2/a3 at +8 feats
    uint32_t qh[4][4], ql[4][4];
    {
        const float* qg = g_q + ((size_t)b * NSEQ + n0) * DKQ;
        #pragma unroll
        for (int it = 0; it < 8; it++) {
            int i = tid + it * 256;
            int r = i >> 4, c4 = i & 15;
            *(float4*)&sP[r * 68 + 4 * c4] = *(const float4*)&qg[(size_t)r * DKQ + 4 * c4];
        }
        __syncthreads();
        const int r0 = (w * 16 + l4) * 68;
        const int r1 = r0 + 8 * 68;
        #pragma unroll
        for (int kt = 0; kt < 4; kt++) {
            const int d0 = 16 * kt + 2 * lm4;
            float2 va = *(const float2*)&sP[r0 + d0];
            float2 vb = *(const float2*)&sP[r1 + d0];
            float2 vc = *(const float2*)&sP[r0 + d0 + 8];
            float2 vd = *(const float2*)&sP[r1 + d0 + 8];
            uint32_t h;
            h = packbf(va.x, va.y); qh[kt][0] = h;
            ql[kt][0] = packbf(va.x - bf_lo_f(h), va.y - bf_hi_f(h));
            h = packbf(vb.x, vb.y); qh[kt][1] = h;
            ql[kt][1] = packbf(vb.x - bf_lo_f(h), vb.y - bf_hi_f(h));
            h = packbf(vc.x, vc.y); qh[kt][2] = h;
            ql[kt][2] = packbf(vc.x - bf_lo_f(h), vc.y - bf_hi_f(h));
            h = packbf(vd.x, vd.y); qh[kt][3] = h;
            ql[kt][3] = packbf(vd.x - bf_lo_f(h), vd.y - bf_hi_f(h));
        }
    }

    float4 O[32];   // [mb*16+nt]: rows 32rg+16mb+{l4,l4+8}, ch 128cg + nt*8 + 2lm4(+1)
    #pragma unroll
    for (int nt = 0; nt < 32; nt++) O[nt] = make_float4(0.f, 0.f, 0.f, 0.f);
    float lsumA = 0.f, lsumB = 0.f;

    const int prow = (w * 16 + l4) * 68;

    #pragma unroll 1
    for (int t = 0; t < NTILES; t++) {
        // ---- K(t) ready (V(t) may still be in flight) ----
        CP_WAIT(1);
        __syncthreads();

        // ---- S = Qhi*(Khi+Klo) + Qlo*Khi  (bf16x3, k16); rows w*16..+15 ----
        float4 S[8];
        #pragma unroll
        for (int nt = 0; nt < 8; nt++) S[nt] = make_float4(0.f, 0.f, 0.f, 0.f);

        #pragma unroll
        for (int kt = 0; kt < 4; kt++) {
            #pragma unroll
            for (int nt = 0; nt < 8; nt++) {
                const int bc = (nt * 8 + l4) * 40 + kt * 8 + 2 * lm4;
                uint2 kh = *(const uint2*)&sKh[bc];
                uint2 kl = *(const uint2*)&sKl[bc];
                mma16bf(S[nt], qh[kt][0], qh[kt][1], qh[kt][2], qh[kt][3], kh.x, kh.y);
                mma16bf(S[nt], qh[kt][0], qh[kt][1], qh[kt][2], qh[kt][3], kl.x, kl.y);
                mma16bf(S[nt], ql[kt][0], ql[kt][1], ql[kt][2], ql[kt][3], kh.x, kh.y);
            }
        }

        // ---- softmax (log2 domain); P tf32-truncated, lsum from p-hat ----
        #pragma unroll
        for (int nt = 0; nt < 8; nt++) {
            float p0 = tf32_hi(fast_exp2(S[nt].x));
            float p1 = tf32_hi(fast_exp2(S[nt].y));
            float p2 = tf32_hi(fast_exp2(S[nt].z));
            float p3 = tf32_hi(fast_exp2(S[nt].w));
            lsumA += p0 + p1;
            lsumB += p2 + p3;
            const int pc = prow + nt * 8 + 2 * lm4;
            *(float2*)&sP[pc]          = make_float2(p0, p1);
            *(float2*)&sP[pc + 8 * 68] = make_float2(p2, p3);
        }
        __syncthreads();   // all QK reads of K done + P visible block-wide

        // ---- stream K(t+1) into the (now free) K buffer; overlaps PV ----
        if (t + 1 < NTILES) issue_k(b, (t + 1) * BK, tid, smb);
        CP_COMMIT();       // uniform group count (empty group on last tile)

        // ---- V(t) ready ----
        CP_WAIT(1);
        __syncthreads();

        // ---- O += P * V (tf32) : rows [32rg,32rg+32) x channels [128cg,128cg+128) ----
        #pragma unroll 1
        for (int kt = 0; kt < 8; kt++) {
            const int ac0 = (32 * rg + l4) * 68 + kt * 8 + lm4;
            const int ac1 = ac0 + 16 * 68;
            uint32_t pa0 = sPu[ac0],     pa1 = sPu[ac0 + 8 * 68];
            uint32_t pa2 = sPu[ac0 + 4], pa3 = sPu[ac0 + 8 * 68 + 4];
            uint32_t pb0 = sPu[ac1],     pb1 = sPu[ac1 + 8 * 68];
            uint32_t pb2 = sPu[ac1 + 4], pb3 = sPu[ac1 + 8 * 68 + 4];
            const int v0b = (kt * 8 + lm4) * 264 + 128 * cg + l4;
            const int v1b = v0b + 4 * 264;
            #pragma unroll
            for (int nt = 0; nt < 16; nt++) {
                uint32_t v0 = __float_as_uint(sV[v0b + nt * 8]);
                uint32_t v1 = __float_as_uint(sV[v1b + nt * 8]);
                mma8(O[nt],      pa0, pa1, pa2, pa3, v0, v1);
                mma8(O[16 + nt], pb0, pb1, pb2, pb3, v0, v1);
            }
        }
        __syncthreads();   // all PV reads of V done

        // ---- stream V(t+1); overlaps next tile's QK + softmax ----
        if (t + 1 < NTILES) issue_v(b, (t + 1) * BK, tid, smb);
        CP_COMMIT();
    }

    // ---- epilogue: broadcast lsum, normalize, write ----
    lsumA += __shfl_xor_sync(0xffffffffu, lsumA, 1);
    lsumA += __shfl_xor_sync(0xffffffffu, lsumA, 2);
    lsumB += __shfl_xor_sync(0xffffffffu, lsumB, 1);
    lsumB += __shfl_xor_sync(0xffffffffu, lsumB, 2);
    if (lm4 == 0) {
        lrow[w * 16 + l4]     = lsumA;
        lrow[w * 16 + l4 + 8] = lsumB;
    }
    __syncthreads();

    #pragma unroll
    for (int mb = 0; mb < 2; mb++) {
        const int rbase = 32 * rg + 16 * mb + l4;
        float invA = 1.0f / lrow[rbase];
        float invB = 1.0f / lrow[rbase + 8];
        float* ob = out + (size_t)b * DOUT * NSEQ + n0 + rbase;
        #pragma unroll
        for (int nt = 0; nt < 16; nt++) {
            int o = 128 * cg + nt * 8 + 2 * lm4;
            float4 v = O[mb * 16 + nt];
            ob[(size_t)o * NSEQ]           = v.x * invA;
            ob[(size_t)(o + 1) * NSEQ]     = v.y * invA;
            ob[(size_t)o * NSEQ + 8]       = v.z * invB;
            ob[(size_t)(o + 1) * NSEQ + 8] = v.w * invB;
        }
    }
}

extern "C" void kernel_launch(void* const* d_in, const int* in_sizes, int n_in,
                              void* d_out, int out_size) {
    (void)in_sizes; (void)n_in; (void)out_size;
    const float* x  = (const float*)d_in[0];
    const float* Wq = (const float*)d_in[1];
    const float* Wk = (const float*)d_in[2];
    const float* Wv = (const float*)d_in[3];
    float* out = (float*)d_out;

    cudaFuncSetAttribute(attn_mma, cudaFuncAttributeMaxDynamicSharedMemorySize,
                         SMEM_FLOATS * (int)sizeof(float));

    dim3 gp(NSEQ / 64, 6, BATCH);
    proj_kernel<<<gp, 256>>>(x, Wq, Wk, Wv);

    dim3 ga(NSEQ / BM, BATCH);
    attn_mma<<<ga, 256, SMEM_FLOATS * sizeof(float)>>>(out);
}

// round 13
// speedup vs baseline: 1.8670x; 1.1154x over previous
#include <cuda_runtime.h>
#include <cuda_bf16.h>
#include <math.h>
#include <stdint.h>

// Problem constants
#define BATCH 8
#define CIN   256
#define NSEQ  4096
#define DKQ   64
#define DOUT  256

// Attention tiling
#define BM 128
#define BK 64
#define NTILES (NSEQ / BK)

// Scratch (device globals)
__device__ float    g_q[(size_t)BATCH * NSEQ * DKQ];    // [b][n][64], fp32, scaled log2e/8
__device__ uint32_t g_khi[(size_t)BATCH * NSEQ * 32];   // [b][n][32] bf16x2, hi, interleaved
__device__ uint32_t g_klo[(size_t)BATCH * NSEQ * 32];   // [b][n][32] bf16x2, lo, interleaved
__device__ float    g_v[(size_t)BATCH * NSEQ * DOUT];   // [b][n][256], tf32-truncated
__device__ uint32_t g_wh[8 * 384 * 16];                 // W bf16 hi, [chunk][j][16 u32]
__device__ uint32_t g_wl[8 * 384 * 16];                 // W bf16 lo

__device__ __forceinline__ float tf32_hi(float x) {
    return __uint_as_float(__float_as_uint(x) & 0xFFFFE000u);
}
__device__ __forceinline__ float fast_exp2(float x) {
    float r;
    asm("ex2.approx.ftz.f32 %0, %1;" : "=f"(r) : "f"(x));
    return r;
}
__device__ __forceinline__ uint32_t smem_u32(const void* p) {
    uint32_t a;
    asm("{ .reg .u64 t; cvta.to.shared.u64 t, %1; cvt.u32.u64 %0, t; }" : "=r"(a) : "l"(p));
    return a;
}
__device__ __forceinline__ void cp_async16(uint32_t dst, const void* src) {
    asm volatile("cp.async.cg.shared.global [%0], [%1], 16;" :: "r"(dst), "l"(src));
}
#define CP_COMMIT() asm volatile("cp.async.commit_group;" ::: "memory")
#define CP_WAIT(N)  asm volatile("cp.async.wait_group %0;" :: "n"(N) : "memory")

// bf16 pack: u32 with first arg in low half
__device__ __forceinline__ uint32_t packbf(float lo, float hi) {
    __nv_bfloat162 h2 = __floats2bfloat162_rn(lo, hi);
    return *(uint32_t*)&h2;
}
__device__ __forceinline__ float bf_lo_f(uint32_t p) { return __uint_as_float(p << 16); }
__device__ __forceinline__ float bf_hi_f(uint32_t p) { return __uint_as_float(p & 0xFFFF0000u); }

// fragment interleave position for u32 column index (valid for cu in [0,32))
__device__ __forceinline__ int fpos(int cu) {
    return ((cu >> 3) << 3) + ((cu & 3) << 1) + ((cu >> 2) & 1);
}

// m16n8k8 tf32 mma (PV)
__device__ __forceinline__ void mma8(float4& d,
                                     uint32_t a0, uint32_t a1, uint32_t a2, uint32_t a3,
                                     uint32_t b0, uint32_t b1) {
    asm("mma.sync.aligned.m16n8k8.row.col.f32.tf32.tf32.f32 "
        "{%0,%1,%2,%3}, {%4,%5,%6,%7}, {%8,%9}, {%0,%1,%2,%3};"
        : "+f"(d.x), "+f"(d.y), "+f"(d.z), "+f"(d.w)
        : "r"(a0), "r"(a1), "r"(a2), "r"(a3), "r"(b0), "r"(b1));
}
// m16n8k16 bf16 mma (QK + proj)
__device__ __forceinline__ void mma16bf(float4& d,
                                        uint32_t a0, uint32_t a1, uint32_t a2, uint32_t a3,
                                        uint32_t b0, uint32_t b1) {
    asm("mma.sync.aligned.m16n8k16.row.col.f32.bf16.bf16.f32 "
        "{%0,%1,%2,%3}, {%4,%5,%6,%7}, {%8,%9}, {%0,%1,%2,%3};"
        : "+f"(d.x), "+f"(d.y), "+f"(d.z), "+f"(d.w)
        : "r"(a0), "r"(a1), "r"(a2), "r"(a3), "r"(b0), "r"(b1));
}

// ==================== W prep: fp32 -> bf16 hi/lo fragment layout ====================
// j: 0..63 = Wq (scaled), 64..127 = Wk, 128..383 = Wv.
__global__ __launch_bounds__(256) void w_prep(const float* __restrict__ Wq,
                                              const float* __restrict__ Wk,
                                              const float* __restrict__ Wv) {
    int i = blockIdx.x * 256 + threadIdx.x;   // 49152 tasks
    int cu = i & 15;
    int j  = (i >> 4) % 384;
    int ch = i / 6144;
    int c  = ch * 32 + 2 * cu;

    const float* wrow;
    float s;
    if (j < 64)       { wrow = Wq + (size_t)j * CIN;        s = 0.125f * 1.4426950408889634f; }
    else if (j < 128) { wrow = Wk + (size_t)(j - 64) * CIN; s = 1.0f; }
    else              { wrow = Wv + (size_t)(j - 128) * CIN; s = 1.0f; }

    float va = wrow[c] * s;
    float vb = wrow[c + 1] * s;
    uint32_t h = packbf(va, vb);
    uint32_t l = packbf(va - bf_lo_f(h), vb - bf_hi_f(h));
    size_t dst = ((size_t)ch * 384 + j) * 16 + fpos(cu);
    g_wh[dst] = h;
    g_wl[dst] = l;
}

// ==================== tensor-core projection ====================
// CTA: 64 n-rows x all 384 output channels. 256 threads = 8 warps = 4 wr x 2 jh.
// SMEM (u32): swh [384][24] @0, swl @9216, sxh [64][24] @18432, sxl @19968.
#define PW_H 0
#define PW_L 9216
#define PX_H 18432
#define PX_L 19968
#define PROJ_SMEM_U32 21504   // 86016 bytes

__global__ __launch_bounds__(256, 1) void proj_tc(const float* __restrict__ x) {
    extern __shared__ uint32_t su[];
    uint32_t* swh = su + PW_H;
    uint32_t* swl = su + PW_L;
    uint32_t* sxh = su + PX_H;
    uint32_t* sxl = su + PX_L;
    const uint32_t smb = smem_u32(su);

    const int tid = threadIdx.x;
    const int w   = tid >> 5;
    const int ln  = tid & 31;
    const int l4  = ln >> 2;
    const int lm4 = ln & 3;
    const int wr  = w & 3;
    const int jh  = w >> 2;
    const int b   = blockIdx.y;
    const int n0  = blockIdx.x * 64;

    float4 acc[24];
    #pragma unroll
    for (int nt = 0; nt < 24; nt++) acc[nt] = make_float4(0.f, 0.f, 0.f, 0.f);

    #pragma unroll 1
    for (int ch = 0; ch < 8; ch++) {
        __syncthreads();   // previous MMA done reading swh/sxh

        // ---- issue W chunk cp.async (raw, pre-formatted) ----
        #pragma unroll
        for (int it = 0; it < 12; it++) {
            int i = tid + it * 256;              // 3072: 2 arrays x 384 rows x 4 q4
            int arr = (i >= 1536);
            int ii  = i - (arr ? 1536 : 0);      // FIX: 1536 is not a pow2; no masking
            int r   = ii >> 2;
            int q4  = ii & 3;
            const uint32_t* src = (arr ? g_wl : g_wh) + ((size_t)ch * 384 + r) * 16 + q4 * 4;
            uint32_t dst = smb + (uint32_t)((arr ? PW_L : PW_H) + r * 24 + q4 * 4) * 4;
            cp_async16(dst, src);
        }
        CP_COMMIT();

        // ---- x transpose + bf16 hi/lo convert (overlaps W cp.async) ----
        #pragma unroll
        for (int it = 0; it < 2; it++) {
            int i = tid + it * 256;              // 512 tasks: cu 16 x n2 32
            int cu = i & 15, n2 = i >> 4;
            int c = ch * 32 + 2 * cu;
            const float* xp = x + ((size_t)(b * CIN + c)) * NSEQ + n0 + 2 * n2;
            float2 va = *(const float2*)xp;          // row c,   n = 2n2, 2n2+1
            float2 vb = *(const float2*)(xp + NSEQ); // row c+1
            int pos = fpos(cu);
            uint32_t h0 = packbf(va.x, vb.x);
            uint32_t l0 = packbf(va.x - bf_lo_f(h0), vb.x - bf_hi_f(h0));
            uint32_t h1 = packbf(va.y, vb.y);
            uint32_t l1 = packbf(va.y - bf_lo_f(h1), vb.y - bf_hi_f(h1));
            sxh[(2 * n2) * 24 + pos]     = h0;
            sxl[(2 * n2) * 24 + pos]     = l0;
            sxh[(2 * n2 + 1) * 24 + pos] = h1;
            sxl[(2 * n2 + 1) * 24 + pos] = l1;
        }
        CP_WAIT(0);
        __syncthreads();

        // ---- 3-pass bf16 MMA: acc += xhi*(Whi+Wlo) + xlo*Whi ----
        #pragma unroll
        for (int kt = 0; kt < 2; kt++) {
            const int ab = (16 * wr + l4) * 24 + kt * 8 + 2 * lm4;
            uint2 xa = *(const uint2*)&sxh[ab];
            uint2 xb = *(const uint2*)&sxh[ab + 8 * 24];
            uint2 la = *(const uint2*)&sxl[ab];
            uint2 lb = *(const uint2*)&sxl[ab + 8 * 24];
            #pragma unroll
            for (int nt = 0; nt < 24; nt++) {
                const int bc = (jh * 192 + nt * 8 + l4) * 24 + kt * 8 + 2 * lm4;
                uint2 wh2 = *(const uint2*)&swh[bc];
                uint2 wl2 = *(const uint2*)&swl[bc];
                mma16bf(acc[nt], xa.x, xb.x, xa.y, xb.y, wh2.x, wh2.y);
                mma16bf(acc[nt], xa.x, xb.x, xa.y, xb.y, wl2.x, wl2.y);
                mma16bf(acc[nt], la.x, lb.x, la.y, lb.y, wh2.x, wh2.y);
            }
        }
    }

    // ---- epilogue: route to g_q / g_khi+g_klo / g_v ----
    const int r0 = 16 * wr + l4;
    const size_t nrow0 = (size_t)b * NSEQ + n0 + r0;
    const size_t nrow1 = nrow0 + 8;

    if (jh == 0) {
        #pragma unroll
        for (int nt = 0; nt < 24; nt++) {
            float4 d = acc[nt];
            if (nt < 8) {
                int j = nt * 8 + 2 * lm4;
                *(float2*)&g_q[nrow0 * DKQ + j] = make_float2(d.x, d.y);
                *(float2*)&g_q[nrow1 * DKQ + j] = make_float2(d.z, d.w);
            } else if (nt < 16) {
                int cu = (nt - 8) * 4 + lm4;     // u32 col in [0,32)
                int pos = fpos(cu);
                uint32_t h0 = packbf(d.x, d.y);
                uint32_t l0 = packbf(d.x - bf_lo_f(h0), d.y - bf_hi_f(h0));
                uint32_t h1 = packbf(d.z, d.w);
                uint32_t l1 = packbf(d.z - bf_lo_f(h1), d.w - bf_hi_f(h1));
                g_khi[nrow0 * 32 + pos] = h0;
                g_klo[nrow0 * 32 + pos] = l0;
                g_khi[nrow1 * 32 + pos] = h1;
                g_klo[nrow1 * 32 + pos] = l1;
            } else {
                int o = (nt - 16) * 8 + 2 * lm4;
                *(float2*)&g_v[nrow0 * DOUT + o] = make_float2(tf32_hi(d.x), tf32_hi(d.y));
                *(float2*)&g_v[nrow1 * DOUT + o] = make_float2(tf32_hi(d.z), tf32_hi(d.w));
            }
        }
    } else {
        #pragma unroll
        for (int nt = 0; nt < 24; nt++) {
            float4 d = acc[nt];
            int o = 64 + nt * 8 + 2 * lm4;
            *(float2*)&g_v[nrow0 * DOUT + o] = make_float2(tf32_hi(d.x), tf32_hi(d.y));
            *(float2*)&g_v[nrow1 * DOUT + o] = make_float2(tf32_hi(d.z), tf32_hi(d.w));
        }
    }
}

// ==================== cp.async pipelined flash attention (bf16 QK) — unchanged R11 ====================
#define KH_O 0
#define KL_O 2560
#define V_O  5120
#define P_O  22016
#define L_O  30720
#define SMEM_FLOATS 30848   // 123392 bytes

__device__ __forceinline__ void issue_k(int b, int k0, int tid, uint32_t smb) {
    #pragma unroll
    for (int it = 0; it < 4; it++) {
        int i = tid + it * 256;
        int arr = i >> 9, r = (i >> 3) & 63, c = i & 7;
        const uint32_t* src = (arr ? g_klo : g_khi) +
                              ((size_t)b * NSEQ + k0 + r) * 32 + c * 4;
        uint32_t dst = smb + (uint32_t)(arr ? KL_O : KH_O) * 4 + r * 160 + c * 16;
        cp_async16(dst, src);
    }
}
__device__ __forceinline__ void issue_v(int b, int k0, int tid, uint32_t smb) {
    const float* vg = g_v + ((size_t)b * NSEQ + k0) * DOUT;
    #pragma unroll
    for (int it = 0; it < 16; it++) {
        int i = tid + it * 256;
        int r = i >> 6, c4 = i & 63;
        uint32_t dst = smb + (uint32_t)V_O * 4 + r * 1056 + c4 * 16;
        cp_async16(dst, vg + (size_t)r * DOUT + 4 * c4);
    }
}

__global__ __launch_bounds__(256, 1) void attn_mma(float* __restrict__ out) {
    extern __shared__ float sm[];
    const uint32_t* sKh = (const uint32_t*)sm + KH_O;
    const uint32_t* sKl = (const uint32_t*)sm + KL_O;
    float* sV  = sm + V_O;
    float* sP  = sm + P_O;
    float* lrow = sm + L_O;
    const uint32_t* sPu = (const uint32_t*)sP;
    const uint32_t smb = smem_u32(sm);

    const int tid = threadIdx.x;
    const int w   = tid >> 5;
    const int ln  = tid & 31;
    const int l4  = ln >> 2;
    const int lm4 = ln & 3;
    const int rg  = w >> 1;
    const int cg  = w & 1;
    const int b   = blockIdx.y;
    const int n0  = blockIdx.x * BM;

    issue_k(b, 0, tid, smb);
    CP_COMMIT();
    issue_v(b, 0, tid, smb);
    CP_COMMIT();

    uint32_t qh[4][4], ql[4][4];
    {
        const float* qg = g_q + ((size_t)b * NSEQ + n0) * DKQ;
        #pragma unroll
        for (int it = 0; it < 8; it++) {
            int i = tid + it * 256;
            int r = i >> 4, c4 = i & 15;
            *(float4*)&sP[r * 68 + 4 * c4] = *(const float4*)&qg[(size_t)r * DKQ + 4 * c4];
        }
        __syncthreads();
        const int r0 = (w * 16 + l4) * 68;
        const int r1 = r0 + 8 * 68;
        #pragma unroll
        for (int kt = 0; kt < 4; kt++) {
            const int d0 = 16 * kt + 2 * lm4;
            float2 va = *(const float2*)&sP[r0 + d0];
            float2 vb = *(const float2*)&sP[r1 + d0];
            float2 vc = *(const float2*)&sP[r0 + d0 + 8];
            float2 vd = *(const float2*)&sP[r1 + d0 + 8];
            uint32_t h;
            h = packbf(va.x, va.y); qh[kt][0] = h;
            ql[kt][0] = packbf(va.x - bf_lo_f(h), va.y - bf_hi_f(h));
            h = packbf(vb.x, vb.y); qh[kt][1] = h;
            ql[kt][1] = packbf(vb.x - bf_lo_f(h), vb.y - bf_hi_f(h));
            h = packbf(vc.x, vc.y); qh[kt][2] = h;
            ql[kt][2] = packbf(vc.x - bf_lo_f(h), vc.y - bf_hi_f(h));
            h = packbf(vd.x, vd.y); qh[kt][3] = h;
            ql[kt][3] = packbf(vd.x - bf_lo_f(h), vd.y - bf_hi_f(h));
        }
    }

    float4 O[32];
    #pragma unroll
    for (int nt = 0; nt < 32; nt++) O[nt] = make_float4(0.f, 0.f, 0.f, 0.f);
    float lsumA = 0.f, lsumB = 0.f;

    const int prow = (w * 16 + l4) * 68;

    #pragma unroll 1
    for (int t = 0; t < NTILES; t++) {
        CP_WAIT(1);
        __syncthreads();

        float4 S[8];
        #pragma unroll
        for (int nt = 0; nt < 8; nt++) S[nt] = make_float4(0.f, 0.f, 0.f, 0.f);

        #pragma unroll
        for (int kt = 0; kt < 4; kt++) {
            #pragma unroll
            for (int nt = 0; nt < 8; nt++) {
                const int bc = (nt * 8 + l4) * 40 + kt * 8 + 2 * lm4;
                uint2 kh = *(const uint2*)&sKh[bc];
                uint2 kl = *(const uint2*)&sKl[bc];
                mma16bf(S[nt], qh[kt][0], qh[kt][1], qh[kt][2], qh[kt][3], kh.x, kh.y);
                mma16bf(S[nt], qh[kt][0], qh[kt][1], qh[kt][2], qh[kt][3], kl.x, kl.y);
                mma16bf(S[nt], ql[kt][0], ql[kt][1], ql[kt][2], ql[kt][3], kh.x, kh.y);
            }
        }

        #pragma unroll
        for (int nt = 0; nt < 8; nt++) {
            float p0 = tf32_hi(fast_exp2(S[nt].x));
            float p1 = tf32_hi(fast_exp2(S[nt].y));
            float p2 = tf32_hi(fast_exp2(S[nt].z));
            float p3 = tf32_hi(fast_exp2(S[nt].w));
            lsumA += p0 + p1;
            lsumB += p2 + p3;
            const int pc = prow + nt * 8 + 2 * lm4;
            *(float2*)&sP[pc]          = make_float2(p0, p1);
            *(float2*)&sP[pc + 8 * 68] = make_float2(p2, p3);
        }
        __syncthreads();

        if (t + 1 < NTILES) issue_k(b, (t + 1) * BK, tid, smb);
        CP_COMMIT();

        CP_WAIT(1);
        __syncthreads();

        #pragma unroll 1
        for (int kt = 0; kt < 8; kt++) {
            const int ac0 = (32 * rg + l4) * 68 + kt * 8 + lm4;
            const int ac1 = ac0 + 16 * 68;
            uint32_t pa0 = sPu[ac0],     pa1 = sPu[ac0 + 8 * 68];
            uint32_t pa2 = sPu[ac0 + 4], pa3 = sPu[ac0 + 8 * 68 + 4];
            uint32_t pb0 = sPu[ac1],     pb1 = sPu[ac1 + 8 * 68];
            uint32_t pb2 = sPu[ac1 + 4], pb3 = sPu[ac1 + 8 * 68 + 4];
            const int v0b = (kt * 8 + lm4) * 264 + 128 * cg + l4;
            const int v1b = v0b + 4 * 264;
            #pragma unroll
            for (int nt = 0; nt < 16; nt++) {
                uint32_t v0 = __float_as_uint(sV[v0b + nt * 8]);
                uint32_t v1 = __float_as_uint(sV[v1b + nt * 8]);
                mma8(O[nt],      pa0, pa1, pa2, pa3, v0, v1);
                mma8(O[16 + nt], pb0, pb1, pb2, pb3, v0, v1);
            }
        }
        __syncthreads();

        if (t + 1 < NTILES) issue_v(b, (t + 1) * BK, tid, smb);
        CP_COMMIT();
    }

    lsumA += __shfl_xor_sync(0xffffffffu, lsumA, 1);
    lsumA += __shfl_xor_sync(0xffffffffu, lsumA, 2);
    lsumB += __shfl_xor_sync(0xffffffffu, lsumB, 1);
    lsumB += __shfl_xor_sync(0xffffffffu, lsumB, 2);
    if (lm4 == 0) {
        lrow[w * 16 + l4]     = lsumA;
        lrow[w * 16 + l4 + 8] = lsumB;
    }
    __syncthreads();

    #pragma unroll
    for (int mb = 0; mb < 2; mb++) {
        const int rbase = 32 * rg + 16 * mb + l4;
        float invA = 1.0f / lrow[rbase];
        float invB = 1.0f / lrow[rbase + 8];
        float* ob = out + (size_t)b * DOUT * NSEQ + n0 + rbase;
        #pragma unroll
        for (int nt = 0; nt < 16; nt++) {
            int o = 128 * cg + nt * 8 + 2 * lm4;
            float4 v = O[mb * 16 + nt];
            ob[(size_t)o * NSEQ]           = v.x * invA;
            ob[(size_t)(o + 1) * NSEQ]     = v.y * invA;
            ob[(size_t)o * NSEQ + 8]       = v.z * invB;
            ob[(size_t)(o + 1) * NSEQ + 8] = v.w * invB;
        }
    }
}

extern "C" void kernel_launch(void* const* d_in, const int* in_sizes, int n_in,
                              void* d_out, int out_size) {
    (void)in_sizes; (void)n_in; (void)out_size;
    const float* x  = (const float*)d_in[0];
    const float* Wq = (const float*)d_in[1];
    const float* Wk = (const float*)d_in[2];
    const float* Wv = (const float*)d_in[3];
    float* out = (float*)d_out;

    cudaFuncSetAttribute(proj_tc, cudaFuncAttributeMaxDynamicSharedMemorySize,
                         PROJ_SMEM_U32 * (int)sizeof(uint32_t));
    cudaFuncSetAttribute(attn_mma, cudaFuncAttributeMaxDynamicSharedMemorySize,
                         SMEM_FLOATS * (int)sizeof(float));

    w_prep<<<192, 256>>>(Wq, Wk, Wv);

    dim3 gp(NSEQ / 64, BATCH);
    proj_tc<<<gp, 256, PROJ_SMEM_U32 * sizeof(uint32_t)>>>(x);

    dim3 ga(NSEQ / BM, BATCH);
    attn_mma<<<ga, 256, SMEM_FLOATS * sizeof(float)>>>(out);
}

// round 14
// speedup vs baseline: 2.7048x; 1.4487x over previous
#include <cuda_runtime.h>
#include <cuda_bf16.h>
#include <cuda_fp16.h>
#include <math.h>
#include <stdint.h>

// Problem constants
#define BATCH 8
#define CIN   256
#define NSEQ  4096
#define DKQ   64
#define DOUT  256

// Attention tiling
#define BM 128
#define BK 64
#define NTILES (NSEQ / BK)

// Scratch (device globals)
__device__ float    g_q[(size_t)BATCH * NSEQ * DKQ];    // [b][n][64], fp32, scaled log2e/8
__device__ uint32_t g_khi[(size_t)BATCH * NSEQ * 32];   // [b][n][32] bf16x2, hi, interleaved
__device__ uint32_t g_klo[(size_t)BATCH * NSEQ * 32];   // [b][n][32] bf16x2, lo, interleaved
__device__ uint32_t g_v[(size_t)BATCH * (NSEQ/2) * DOUT]; // [b][kp][ch] fp16x2 (rows 2kp,2kp+1)
__device__ uint32_t g_wh[8 * 384 * 16];                 // W bf16 hi, [chunk][j][16 u32]
__device__ uint32_t g_wl[8 * 384 * 16];                 // W bf16 lo

__device__ __forceinline__ float fast_exp2(float x) {
    float r;
    asm("ex2.approx.ftz.f32 %0, %1;" : "=f"(r) : "f"(x));
    return r;
}
__device__ __forceinline__ uint32_t smem_u32(const void* p) {
    uint32_t a;
    asm("{ .reg .u64 t; cvta.to.shared.u64 t, %1; cvt.u32.u64 %0, t; }" : "=r"(a) : "l"(p));
    return a;
}
__device__ __forceinline__ void cp_async16(uint32_t dst, const void* src) {
    asm volatile("cp.async.cg.shared.global [%0], [%1], 16;" :: "r"(dst), "l"(src));
}
#define CP_COMMIT() asm volatile("cp.async.commit_group;" ::: "memory")
#define CP_WAIT(N)  asm volatile("cp.async.wait_group %0;" :: "n"(N) : "memory")

// bf16 pack: u32 with first arg in low half
__device__ __forceinline__ uint32_t packbf(float lo, float hi) {
    __nv_bfloat162 h2 = __floats2bfloat162_rn(lo, hi);
    return *(uint32_t*)&h2;
}
__device__ __forceinline__ float bf_lo_f(uint32_t p) { return __uint_as_float(p << 16); }
__device__ __forceinline__ float bf_hi_f(uint32_t p) { return __uint_as_float(p & 0xFFFF0000u); }
// fp16 pack: u32 with first arg in low half
__device__ __forceinline__ uint32_t packh(float lo, float hi) {
    __half2 h2 = __floats2half2_rn(lo, hi);
    return *(uint32_t*)&h2;
}

// fragment interleave position for u32 column index (valid for cu in [0,32))
__device__ __forceinline__ int fpos(int cu) {
    return ((cu >> 3) << 3) + ((cu & 3) << 1) + ((cu >> 2) & 1);
}

// m16n8k16 bf16 mma (QK + proj)
__device__ __forceinline__ void mma16bf(float4& d,
                                        uint32_t a0, uint32_t a1, uint32_t a2, uint32_t a3,
                                        uint32_t b0, uint32_t b1) {
    asm("mma.sync.aligned.m16n8k16.row.col.f32.bf16.bf16.f32 "
        "{%0,%1,%2,%3}, {%4,%5,%6,%7}, {%8,%9}, {%0,%1,%2,%3};"
        : "+f"(d.x), "+f"(d.y), "+f"(d.z), "+f"(d.w)
        : "r"(a0), "r"(a1), "r"(a2), "r"(a3), "r"(b0), "r"(b1));
}
// m16n8k16 fp16 mma (PV)
__device__ __forceinline__ void mma16h(float4& d,
                                       uint32_t a0, uint32_t a1, uint32_t a2, uint32_t a3,
                                       uint32_t b0, uint32_t b1) {
    asm("mma.sync.aligned.m16n8k16.row.col.f32.f16.f16.f32 "
        "{%0,%1,%2,%3}, {%4,%5,%6,%7}, {%8,%9}, {%0,%1,%2,%3};"
        : "+f"(d.x), "+f"(d.y), "+f"(d.z), "+f"(d.w)
        : "r"(a0), "r"(a1), "r"(a2), "r"(a3), "r"(b0), "r"(b1));
}

// ==================== W prep: fp32 -> bf16 hi/lo fragment layout ====================
__global__ __launch_bounds__(256) void w_prep(const float* __restrict__ Wq,
                                              const float* __restrict__ Wk,
                                              const float* __restrict__ Wv) {
    int i = blockIdx.x * 256 + threadIdx.x;   // 49152 tasks
    int cu = i & 15;
    int j  = (i >> 4) % 384;
    int ch = i / 6144;
    int c  = ch * 32 + 2 * cu;

    const float* wrow;
    float s;
    if (j < 64)       { wrow = Wq + (size_t)j * CIN;        s = 0.125f * 1.4426950408889634f; }
    else if (j < 128) { wrow = Wk + (size_t)(j - 64) * CIN; s = 1.0f; }
    else              { wrow = Wv + (size_t)(j - 128) * CIN; s = 1.0f; }

    float va = wrow[c] * s;
    float vb = wrow[c + 1] * s;
    uint32_t h = packbf(va, vb);
    uint32_t l = packbf(va - bf_lo_f(h), vb - bf_hi_f(h));
    size_t dst = ((size_t)ch * 384 + j) * 16 + fpos(cu);
    g_wh[dst] = h;
    g_wl[dst] = l;
}

// ==================== tensor-core projection ====================
// SMEM (u32): swh [384][24] @0, swl @9216, sxh [64][24] @18432, sxl @19968.
#define PW_H 0
#define PW_L 9216
#define PX_H 18432
#define PX_L 19968
#define PROJ_SMEM_U32 21504   // 86016 bytes

__global__ __launch_bounds__(256, 1) void proj_tc(const float* __restrict__ x) {
    extern __shared__ uint32_t su[];
    uint32_t* swh = su + PW_H;
    uint32_t* swl = su + PW_L;
    uint32_t* sxh = su + PX_H;
    uint32_t* sxl = su + PX_L;
    const uint32_t smb = smem_u32(su);

    const int tid = threadIdx.x;
    const int w   = tid >> 5;
    const int ln  = tid & 31;
    const int l4  = ln >> 2;
    const int lm4 = ln & 3;
    const int wr  = w & 3;
    const int jh  = w >> 2;
    const int b   = blockIdx.y;
    const int n0  = blockIdx.x * 64;

    float4 acc[24];
    #pragma unroll
    for (int nt = 0; nt < 24; nt++) acc[nt] = make_float4(0.f, 0.f, 0.f, 0.f);

    #pragma unroll 1
    for (int ch = 0; ch < 8; ch++) {
        __syncthreads();

        #pragma unroll
        for (int it = 0; it < 12; it++) {
            int i = tid + it * 256;              // 3072: 2 arrays x 384 rows x 4 q4
            int arr = (i >= 1536);
            int ii  = i - (arr ? 1536 : 0);
            int r   = ii >> 2;
            int q4  = ii & 3;
            const uint32_t* src = (arr ? g_wl : g_wh) + ((size_t)ch * 384 + r) * 16 + q4 * 4;
            uint32_t dst = smb + (uint32_t)((arr ? PW_L : PW_H) + r * 24 + q4 * 4) * 4;
            cp_async16(dst, src);
        }
        CP_COMMIT();

        #pragma unroll
        for (int it = 0; it < 2; it++) {
            int i = tid + it * 256;              // 512 tasks: cu 16 x n2 32
            int cu = i & 15, n2 = i >> 4;
            int c = ch * 32 + 2 * cu;
            const float* xp = x + ((size_t)(b * CIN + c)) * NSEQ + n0 + 2 * n2;
            float2 va = *(const float2*)xp;
            float2 vb = *(const float2*)(xp + NSEQ);
            int pos = fpos(cu);
            uint32_t h0 = packbf(va.x, vb.x);
            uint32_t l0 = packbf(va.x - bf_lo_f(h0), vb.x - bf_hi_f(h0));
            uint32_t h1 = packbf(va.y, vb.y);
            uint32_t l1 = packbf(va.y - bf_lo_f(h1), vb.y - bf_hi_f(h1));
            sxh[(2 * n2) * 24 + pos]     = h0;
            sxl[(2 * n2) * 24 + pos]     = l0;
            sxh[(2 * n2 + 1) * 24 + pos] = h1;
            sxl[(2 * n2 + 1) * 24 + pos] = l1;
        }
        CP_WAIT(0);
        __syncthreads();

        #pragma unroll
        for (int kt = 0; kt < 2; kt++) {
            const int ab = (16 * wr + l4) * 24 + kt * 8 + 2 * lm4;
            uint2 xa = *(const uint2*)&sxh[ab];
            uint2 xb = *(const uint2*)&sxh[ab + 8 * 24];
            uint2 la = *(const uint2*)&sxl[ab];
            uint2 lb = *(const uint2*)&sxl[ab + 8 * 24];
            #pragma unroll
            for (int nt = 0; nt < 24; nt++) {
                const int bc = (jh * 192 + nt * 8 + l4) * 24 + kt * 8 + 2 * lm4;
                uint2 wh2 = *(const uint2*)&swh[bc];
                uint2 wl2 = *(const uint2*)&swl[bc];
                mma16bf(acc[nt], xa.x, xb.x, xa.y, xb.y, wh2.x, wh2.y);
                mma16bf(acc[nt], xa.x, xb.x, xa.y, xb.y, wl2.x, wl2.y);
                mma16bf(acc[nt], la.x, lb.x, la.y, lb.y, wh2.x, wh2.y);
            }
        }
    }

    // ---- epilogue: route to g_q / g_khi+g_klo / g_v(fp16 kpair-packed) ----
    const int r0 = 16 * wr + l4;
    const size_t nrow0 = (size_t)b * NSEQ + n0 + r0;
    const size_t nrow1 = nrow0 + 8;
    // V pair bases (valid when l4 even): rows (r0, r0+1) and (r0+8, r0+9)
    const size_t vb0 = ((size_t)b * (NSEQ / 2) + ((n0 + r0) >> 1)) * DOUT;
    const size_t vb1 = ((size_t)b * (NSEQ / 2) + ((n0 + r0 + 8) >> 1)) * DOUT;
    const bool vwrite = ((l4 & 1) == 0);

    if (jh == 0) {
        #pragma unroll
        for (int nt = 0; nt < 24; nt++) {
            float4 d = acc[nt];
            if (nt < 8) {
                int j = nt * 8 + 2 * lm4;
                *(float2*)&g_q[nrow0 * DKQ + j] = make_float2(d.x, d.y);
                *(float2*)&g_q[nrow1 * DKQ + j] = make_float2(d.z, d.w);
            } else if (nt < 16) {
                int cu = (nt - 8) * 4 + lm4;
                int pos = fpos(cu);
                uint32_t h0 = packbf(d.x, d.y);
                uint32_t l0 = packbf(d.x - bf_lo_f(h0), d.y - bf_hi_f(h0));
                uint32_t h1 = packbf(d.z, d.w);
                uint32_t l1 = packbf(d.z - bf_lo_f(h1), d.w - bf_hi_f(h1));
                g_khi[nrow0 * 32 + pos] = h0;
                g_klo[nrow0 * 32 + pos] = l0;
                g_khi[nrow1 * 32 + pos] = h1;
                g_klo[nrow1 * 32 + pos] = l1;
            } else {
                int o = (nt - 16) * 8 + 2 * lm4;
                float px = __uint_as_float(__shfl_down_sync(0xffffffffu, __float_as_uint(d.x), 4));
                float py = __uint_as_float(__shfl_down_sync(0xffffffffu, __float_as_uint(d.y), 4));
                float pz = __uint_as_float(__shfl_down_sync(0xffffffffu, __float_as_uint(d.z), 4));
                float pw = __uint_as_float(__shfl_down_sync(0xffffffffu, __float_as_uint(d.w), 4));
                if (vwrite) {
                    g_v[vb0 + o]     = packh(d.x, px);
                    g_v[vb0 + o + 1] = packh(d.y, py);
                    g_v[vb1 + o]     = packh(d.z, pz);
                    g_v[vb1 + o + 1] = packh(d.w, pw);
                }
            }
        }
    } else {
        #pragma unroll
        for (int nt = 0; nt < 24; nt++) {
            float4 d = acc[nt];
            int o = 64 + nt * 8 + 2 * lm4;
            float px = __uint_as_float(__shfl_down_sync(0xffffffffu, __float_as_uint(d.x), 4));
            float py = __uint_as_float(__shfl_down_sync(0xffffffffu, __float_as_uint(d.y), 4));
            float pz = __uint_as_float(__shfl_down_sync(0xffffffffu, __float_as_uint(d.z), 4));
            float pw = __uint_as_float(__shfl_down_sync(0xffffffffu, __float_as_uint(d.w), 4));
            if (vwrite) {
                g_v[vb0 + o]     = packh(d.x, px);
                g_v[vb0 + o + 1] = packh(d.y, py);
                g_v[vb1 + o]     = packh(d.z, pz);
                g_v[vb1 + o + 1] = packh(d.w, pw);
            }
        }
    }
}

// ==================== cp.async pipelined flash attention (bf16 QK, fp16 PV) ====================
// SMEM (u32 units):
//   sKh [64][40] @0 (2560), sKl @2560
//   sV  [32][264] @5120 (8448)  -- kpair rows, fp16x2
//   sP  [128][36] @13568 (4608) -- fp16x2 key pairs
//   lrow @18176 (128 f)
// Q staging (prologue only): floats at u32 offset 5120 (size 8704 <= 13056 free)
#define KH_O 0
#define KL_O 2560
#define V_O  5120
#define P_O  13568
#define L_O  18176
#define ATT_SMEM_U32 18304   // 73216 bytes

__device__ __forceinline__ void issue_k(int b, int k0, int tid, uint32_t smb) {
    #pragma unroll
    for (int it = 0; it < 4; it++) {
        int i = tid + it * 256;              // 1024 chunks: 2 arrays x 64 rows x 8
        int arr = i >> 9, r = (i >> 3) & 63, c = i & 7;
        const uint32_t* src = (arr ? g_klo : g_khi) +
                              ((size_t)b * NSEQ + k0 + r) * 32 + c * 4;
        uint32_t dst = smb + (uint32_t)(arr ? KL_O : KH_O) * 4 + r * 160 + c * 16;
        cp_async16(dst, src);
    }
}
__device__ __forceinline__ void issue_v(int b, int k0, int tid, uint32_t smb) {
    const uint32_t* vg = g_v + ((size_t)b * (NSEQ / 2) + k0 / 2) * DOUT;
    #pragma unroll
    for (int it = 0; it < 8; it++) {
        int i = tid + it * 256;              // 2048 chunks: 32 kpair rows x 64
        int r = i >> 6, c4 = i & 63;
        uint32_t dst = smb + (uint32_t)V_O * 4 + r * 1056 + c4 * 16;
        cp_async16(dst, vg + (size_t)r * DOUT + 4 * c4);
    }
}

__global__ __launch_bounds__(256, 1) void attn_mma(float* __restrict__ out) {
    extern __shared__ uint32_t su[];
    const uint32_t* sKh = su + KH_O;
    const uint32_t* sKl = su + KL_O;
    const uint32_t* sVu = su + V_O;
    uint32_t* sPu = su + P_O;
    float* lrow = (float*)(su + L_O);
    float* sQf = (float*)(su + V_O);   // prologue staging
    const uint32_t smb = smem_u32(su);

    const int tid = threadIdx.x;
    const int w   = tid >> 5;
    const int ln  = tid & 31;
    const int l4  = ln >> 2;
    const int lm4 = ln & 3;
    const int rg  = w >> 1;
    const int cg  = w & 1;
    const int b   = blockIdx.y;
    const int n0  = blockIdx.x * BM;

    // K(0) in flight during Q staging (disjoint smem regions)
    issue_k(b, 0, tid, smb);
    CP_COMMIT();

    // ---- stage Q (fp32) through V region, build bf16 hi/lo A-fragments ----
    uint32_t qh[4][4], ql[4][4];
    {
        const float* qg = g_q + ((size_t)b * NSEQ + n0) * DKQ;
        #pragma unroll
        for (int it = 0; it < 8; it++) {
            int i = tid + it * 256;
            int r = i >> 4, c4 = i & 15;
            *(float4*)&sQf[r * 68 + 4 * c4] = *(const float4*)&qg[(size_t)r * DKQ + 4 * c4];
        }
        __syncthreads();
        const int r0 = (w * 16 + l4) * 68;
        const int r1 = r0 + 8 * 68;
        #pragma unroll
        for (int kt = 0; kt < 4; kt++) {
            const int d0 = 16 * kt + 2 * lm4;
            float2 va = *(const float2*)&sQf[r0 + d0];
            float2 vb = *(const float2*)&sQf[r1 + d0];
            float2 vc = *(const float2*)&sQf[r0 + d0 + 8];
            float2 vd = *(const float2*)&sQf[r1 + d0 + 8];
            uint32_t h;
            h = packbf(va.x, va.y); qh[kt][0] = h;
            ql[kt][0] = packbf(va.x - bf_lo_f(h), va.y - bf_hi_f(h));
            h = packbf(vb.x, vb.y); qh[kt][1] = h;
            ql[kt][1] = packbf(vb.x - bf_lo_f(h), vb.y - bf_hi_f(h));
            h = packbf(vc.x, vc.y); qh[kt][2] = h;
            ql[kt][2] = packbf(vc.x - bf_lo_f(h), vc.y - bf_hi_f(h));
            h = packbf(vd.x, vd.y); qh[kt][3] = h;
            ql[kt][3] = packbf(vd.x - bf_lo_f(h), vd.y - bf_hi_f(h));
        }
        __syncthreads();   // done reading staging before V(0) overwrites it
    }
    issue_v(b, 0, tid, smb);
    CP_COMMIT();

    float4 O[32];
    #pragma unroll
    for (int nt = 0; nt < 32; nt++) O[nt] = make_float4(0.f, 0.f, 0.f, 0.f);
    float lsumA = 0.f, lsumB = 0.f;

    const int prow = (w * 16 + l4) * 36;

    #pragma unroll 1
    for (int t = 0; t < NTILES; t++) {
        // K(t) ready (V(t) may still be in flight)
        CP_WAIT(1);
        __syncthreads();

        // ---- S = Qhi*(Khi+Klo) + Qlo*Khi  (bf16x3) ----
        float4 S[8];
        #pragma unroll
        for (int nt = 0; nt < 8; nt++) S[nt] = make_float4(0.f, 0.f, 0.f, 0.f);

        #pragma unroll
        for (int kt = 0; kt < 4; kt++) {
            #pragma unroll
            for (int nt = 0; nt < 8; nt++) {
                const int bc = (nt * 8 + l4) * 40 + kt * 8 + 2 * lm4;
                uint2 kh = *(const uint2*)&sKh[bc];
                uint2 kl = *(const uint2*)&sKl[bc];
                mma16bf(S[nt], qh[kt][0], qh[kt][1], qh[kt][2], qh[kt][3], kh.x, kh.y);
                mma16bf(S[nt], qh[kt][0], qh[kt][1], qh[kt][2], qh[kt][3], kl.x, kl.y);
                mma16bf(S[nt], ql[kt][0], ql[kt][1], ql[kt][2], ql[kt][3], kh.x, kh.y);
            }
        }

        // ---- softmax (log2 domain); P -> fp16 pairs; lsum in fp32 ----
        #pragma unroll
        for (int nt = 0; nt < 8; nt++) {
            float p0 = fast_exp2(S[nt].x);
            float p1 = fast_exp2(S[nt].y);
            float p2 = fast_exp2(S[nt].z);
            float p3 = fast_exp2(S[nt].w);
            lsumA += p0 + p1;
            lsumB += p2 + p3;
            const int pc = prow + nt * 4 + lm4;
            sPu[pc]          = packh(p0, p1);
            sPu[pc + 8 * 36] = packh(p2, p3);
        }
        __syncthreads();   // QK done with K; P visible block-wide

        if (t + 1 < NTILES) issue_k(b, (t + 1) * BK, tid, smb);
        CP_COMMIT();

        // V(t) ready
        CP_WAIT(1);
        __syncthreads();

        // ---- O += P * V (fp16 k16) : rows [32rg,+32) x channels [128cg,+128) ----
        #pragma unroll
        for (int kt = 0; kt < 4; kt++) {
            const int ac0 = (32 * rg + l4) * 36 + 8 * kt + lm4;
            const int ac1 = ac0 + 16 * 36;
            uint32_t pa0 = sPu[ac0],     pa1 = sPu[ac0 + 8 * 36];
            uint32_t pa2 = sPu[ac0 + 4], pa3 = sPu[ac0 + 8 * 36 + 4];
            uint32_t pb0 = sPu[ac1],     pb1 = sPu[ac1 + 8 * 36];
            uint32_t pb2 = sPu[ac1 + 4], pb3 = sPu[ac1 + 8 * 36 + 4];
            const int v0b = (8 * kt + lm4) * 264 + 128 * cg + l4;
            const int v1b = v0b + 4 * 264;
            #pragma unroll
            for (int nt = 0; nt < 16; nt++) {
                uint32_t v0 = sVu[v0b + nt * 8];
                uint32_t v1 = sVu[v1b + nt * 8];
                mma16h(O[nt],      pa0, pa1, pa2, pa3, v0, v1);
                mma16h(O[16 + nt], pb0, pb1, pb2, pb3, v0, v1);
            }
        }
        __syncthreads();   // PV done with V

        if (t + 1 < NTILES) issue_v(b, (t + 1) * BK, tid, smb);
        CP_COMMIT();
    }

    // ---- epilogue ----
    lsumA += __shfl_xor_sync(0xffffffffu, lsumA, 1);
    lsumA += __shfl_xor_sync(0xffffffffu, lsumA, 2);
    lsumB += __shfl_xor_sync(0xffffffffu, lsumB, 1);
    lsumB += __shfl_xor_sync(0xffffffffu, lsumB, 2);
    if (lm4 == 0) {
        lrow[w * 16 + l4]     = lsumA;
        lrow[w * 16 + l4 + 8] = lsumB;
    }
    __syncthreads();

    #pragma unroll
    for (int mb = 0; mb < 2; mb++) {
        const int rbase = 32 * rg + 16 * mb + l4;
        float invA = 1.0f / lrow[rbase];
        float invB = 1.0f / lrow[rbase + 8];
        float* ob = out + (size_t)b * DOUT * NSEQ + n0 + rbase;
        #pragma unroll
        for (int nt = 0; nt < 16; nt++) {
            int o = 128 * cg + nt * 8 + 2 * lm4;
            float4 v = O[mb * 16 + nt];
            ob[(size_t)o * NSEQ]           = v.x * invA;
            ob[(size_t)(o + 1) * NSEQ]     = v.y * invA;
            ob[(size_t)o * NSEQ + 8]       = v.z * invB;
            ob[(size_t)(o + 1) * NSEQ + 8] = v.w * invB;
        }
    }
}

extern "C" void kernel_launch(void* const* d_in, const int* in_sizes, int n_in,
                              void* d_out, int out_size) {
    (void)in_sizes; (void)n_in; (void)out_size;
    const float* x  = (const float*)d_in[0];
    const float* Wq = (const float*)d_in[1];
    const float* Wk = (const float*)d_in[2];
    const float* Wv = (const float*)d_in[3];
    float* out = (float*)d_out;

    cudaFuncSetAttribute(proj_tc, cudaFuncAttributeMaxDynamicSharedMemorySize,
                         PROJ_SMEM_U32 * (int)sizeof(uint32_t));
    cudaFuncSetAttribute(attn_mma, cudaFuncAttributeMaxDynamicSharedMemorySize,
                         ATT_SMEM_U32 * (int)sizeof(uint32_t));

    w_prep<<<192, 256>>>(Wq, Wk, Wv);

    dim3 gp(NSEQ / 64, BATCH);
    proj_tc<<<gp, 256, PROJ_SMEM_U32 * sizeof(uint32_t)>>>(x);

    dim3 ga(NSEQ / BM, BATCH);
    attn_mma<<<ga, 256, ATT_SMEM_U32 * sizeof(uint32_t)>>>(out);
}